// round 4
// baseline (speedup 1.0000x reference)
#include <cuda_runtime.h>
#include <cuda_bf16.h>
#include <math.h>
#include <stdint.h>

// Problem dims
#define BSZ     2
#define LSEQ    2048
#define DMODEL  2048
#define INTER   4096
#define NHEADS  64
#define PDIM    64
#define NSTATE  128
#define KCONV   4
#define CONV_DIM (INTER + 2*NSTATE)   // 4352
#define TOKENS  (BSZ*LSEQ)            // 4096
#define DTPAD   128
#define EPS     1e-5f

// ---------------- scratch (device globals; no allocation allowed) ----------
__device__ __align__(16) float g_gate[TOKENS*INTER];
__device__ __align__(16) float g_xBC[TOKENS*CONV_DIM];
__device__ __align__(16) float g_xBCc[TOKENS*CONV_DIM];
__device__ __align__(16) float g_dt[TOKENS*DTPAD];     // padded to 128 cols
__device__ __align__(16) float g_y[TOKENS*INTER];

// split-bf16 operands for tensor-core GEMMs
__device__ __align__(16) __nv_bfloat16 g_hs_hi[TOKENS*DMODEL];
__device__ __align__(16) __nv_bfloat16 g_hs_lo[TOKENS*DMODEL];
__device__ __align__(16) __nv_bfloat16 g_Wz_hi[INTER*DMODEL];     // transposed [N,K]
__device__ __align__(16) __nv_bfloat16 g_Wz_lo[INTER*DMODEL];
__device__ __align__(16) __nv_bfloat16 g_WxBC_hi[CONV_DIM*DMODEL];
__device__ __align__(16) __nv_bfloat16 g_WxBC_lo[CONV_DIM*DMODEL];
__device__ __align__(16) __nv_bfloat16 g_Wdt_hi[DTPAD*DMODEL];
__device__ __align__(16) __nv_bfloat16 g_Wdt_lo[DTPAD*DMODEL];
__device__ __align__(16) __nv_bfloat16 g_Wout_hi[DMODEL*INTER];
__device__ __align__(16) __nv_bfloat16 g_Wout_lo[DMODEL*INTER];
__device__ __align__(16) __nv_bfloat16 g_norm_hi[TOKENS*INTER];
__device__ __align__(16) __nv_bfloat16 g_norm_lo[TOKENS*INTER];

// ---------------- PTX helpers ----------------------------------------------
__device__ __forceinline__ uint32_t smem_u32(const void* p) {
    uint32_t a;
    asm("{ .reg .u64 t; cvta.to.shared.u64 t, %1; cvt.u32.u64 %0, t; }"
        : "=r"(a) : "l"(p));
    return a;
}
__device__ __forceinline__ void cp16(uint32_t dst, const void* src) {
    asm volatile("cp.async.cg.shared.global [%0], [%1], 16;"
                 :: "r"(dst), "l"(src) : "memory");
}
__device__ __forceinline__ void cp_commit() {
    asm volatile("cp.async.commit_group;" ::: "memory");
}
template<int PENDING>
__device__ __forceinline__ void cp_wait() {
    asm volatile("cp.async.wait_group %0;" :: "n"(PENDING) : "memory");
}
__device__ __forceinline__ void ldm_x4(uint32_t addr, uint32_t* r) {
    asm volatile("ldmatrix.sync.aligned.m8n8.x4.shared.b16 {%0,%1,%2,%3}, [%4];"
                 : "=r"(r[0]), "=r"(r[1]), "=r"(r[2]), "=r"(r[3]) : "r"(addr));
}
__device__ __forceinline__ void mma_bf16(float* c, const uint32_t* a, const uint32_t* b) {
    asm volatile(
        "mma.sync.aligned.m16n8k16.row.col.f32.bf16.bf16.f32 "
        "{%0,%1,%2,%3}, {%4,%5,%6,%7}, {%8,%9}, {%0,%1,%2,%3};"
        : "+f"(c[0]), "+f"(c[1]), "+f"(c[2]), "+f"(c[3])
        : "r"(a[0]), "r"(a[1]), "r"(a[2]), "r"(a[3]), "r"(b[0]), "r"(b[1]));
}

// ---------------- HMMA GEMM: C[M,N] = A[M,K] @ Bt[N,K]^T -------------------
// A, Bt split bf16 (hi, lo); computes HH + HL + LH in fp32 accumulators.
// M, N multiples of 128; K multiple of 64.
__global__ void __launch_bounds__(256) gemm_mma(
    const __nv_bfloat16* __restrict__ Ahi, const __nv_bfloat16* __restrict__ Alo,
    const __nv_bfloat16* __restrict__ Bhi, const __nv_bfloat16* __restrict__ Blo,
    float* __restrict__ C, int M, int N, int K)
{
    extern __shared__ char smem[];
    uint32_t sbase = smem_u32(smem);
    const int TB = 16384;              // one 128x64 bf16 tile (128B rows, SW128)
    const int STAGE = 4 * TB;          // Ahi, Alo, Bhi, Blo

    int tid = threadIdx.x;
    int lane = tid & 31, wid = tid >> 5;
    int wm = wid & 3, wn = wid >> 2;   // warp tile: 32 x 64
    int brow = blockIdx.y * 128, bcol = blockIdx.x * 128;

    const __nv_bfloat16* src0 = Ahi + (size_t)brow * K;
    const __nv_bfloat16* src1 = Alo + (size_t)brow * K;
    const __nv_bfloat16* src2 = Bhi + (size_t)bcol * K;
    const __nv_bfloat16* src3 = Blo + (size_t)bcol * K;
    int nch = K >> 6;

    auto issue = [&](int ch) {
        uint32_t stage = sbase + (uint32_t)(ch & 1) * STAGE;
        const __nv_bfloat16* srcs[4] = {src0, src1, src2, src3};
        #pragma unroll
        for (int t = 0; t < 4; t++) {
            const __nv_bfloat16* P = srcs[t];
            uint32_t tb = stage + (uint32_t)t * TB;
            #pragma unroll
            for (int i = 0; i < 4; i++) {
                int c = tid + i * 256;          // 0..1023 16B chunks
                int row = c >> 3, u = c & 7;
                uint32_t dst = tb + (uint32_t)(row * 128 + ((u ^ (row & 7)) << 4));
                cp16(dst, P + (size_t)row * K + (size_t)ch * 64 + u * 8);
            }
        }
        cp_commit();
    };

    float acc[2][8][4];
    #pragma unroll
    for (int mf = 0; mf < 2; mf++)
        #pragma unroll
        for (int nf = 0; nf < 8; nf++)
            #pragma unroll
            for (int j = 0; j < 4; j++) acc[mf][nf][j] = 0.f;

    issue(0);
    issue(1);

    for (int ch = 0; ch < nch; ch++) {
        if (ch + 1 < nch) cp_wait<1>(); else cp_wait<0>();
        __syncthreads();
        uint32_t stage = sbase + (uint32_t)(ch & 1) * STAGE;

        #pragma unroll
        for (int ks = 0; ks < 4; ks++) {
            uint32_t aH[2][4], aL[2][4];
            #pragma unroll
            for (int mf = 0; mf < 2; mf++) {
                int row = wm * 32 + mf * 16 + (lane & 7) + ((lane >> 3) & 1) * 8;
                int u   = ks * 2 + ((lane >> 4) & 1);
                uint32_t off = (uint32_t)(row * 128 + ((u ^ (row & 7)) << 4));
                ldm_x4(stage + 0 * TB + off, aH[mf]);
                ldm_x4(stage + 1 * TB + off, aL[mf]);
            }
            uint32_t bH[8][2], bL[8][2];
            #pragma unroll
            for (int ng = 0; ng < 4; ng++) {
                int row = wn * 64 + ng * 16 + (lane & 7) + ((lane >> 4) & 1) * 8;
                int u   = ks * 2 + ((lane >> 3) & 1);
                uint32_t off = (uint32_t)(row * 128 + ((u ^ (row & 7)) << 4));
                uint32_t rH[4], rL[4];
                ldm_x4(stage + 2 * TB + off, rH);
                ldm_x4(stage + 3 * TB + off, rL);
                bH[2*ng][0] = rH[0]; bH[2*ng][1] = rH[1];
                bH[2*ng+1][0] = rH[2]; bH[2*ng+1][1] = rH[3];
                bL[2*ng][0] = rL[0]; bL[2*ng][1] = rL[1];
                bL[2*ng+1][0] = rL[2]; bL[2*ng+1][1] = rL[3];
            }
            #pragma unroll
            for (int mf = 0; mf < 2; mf++)
                #pragma unroll
                for (int nf = 0; nf < 8; nf++) {
                    mma_bf16(acc[mf][nf], aH[mf], bH[nf]);
                    mma_bf16(acc[mf][nf], aH[mf], bL[nf]);
                    mma_bf16(acc[mf][nf], aL[mf], bH[nf]);
                }
        }
        __syncthreads();
        if (ch + 2 < nch) issue(ch + 2);
    }

    #pragma unroll
    for (int mf = 0; mf < 2; mf++) {
        int row = brow + wm * 32 + mf * 16 + (lane >> 2);
        #pragma unroll
        for (int nf = 0; nf < 8; nf++) {
            int col = bcol + wn * 64 + nf * 8 + (lane & 3) * 2;
            *(float2*)&C[(size_t)row * N + col] =
                make_float2(acc[mf][nf][0], acc[mf][nf][1]);
            *(float2*)&C[(size_t)(row + 8) * N + col] =
                make_float2(acc[mf][nf][2], acc[mf][nf][3]);
        }
    }
}

// ---------------- fp32 -> (hi,lo) bf16 split, elementwise ------------------
__global__ void __launch_bounds__(256) split8_kernel(
    const float* __restrict__ x, __nv_bfloat16* __restrict__ hi,
    __nv_bfloat16* __restrict__ lo, int n)
{
    int i = (blockIdx.x * 256 + threadIdx.x) * 8;
    if (i >= n) return;
    float4 a = *(const float4*)(x + i);
    float4 b = *(const float4*)(x + i + 4);
    float v[8] = {a.x, a.y, a.z, a.w, b.x, b.y, b.z, b.w};
    uint32_t hp[4], lp[4];
    #pragma unroll
    for (int j = 0; j < 4; j++) {
        __nv_bfloat16 h0 = __float2bfloat16(v[2*j]);
        __nv_bfloat16 h1 = __float2bfloat16(v[2*j+1]);
        __nv_bfloat16 l0 = __float2bfloat16(v[2*j]   - __bfloat162float(h0));
        __nv_bfloat16 l1 = __float2bfloat16(v[2*j+1] - __bfloat162float(h1));
        __nv_bfloat162 hh = __halves2bfloat162(h0, h1);
        __nv_bfloat162 ll = __halves2bfloat162(l0, l1);
        hp[j] = *(uint32_t*)&hh;
        lp[j] = *(uint32_t*)&ll;
    }
    *(uint4*)(hi + i) = make_uint4(hp[0], hp[1], hp[2], hp[3]);
    *(uint4*)(lo + i) = make_uint4(lp[0], lp[1], lp[2], lp[3]);
}

// ---------------- W[K,N] -> Wt[N,K] with bf16 split ------------------------
__global__ void __launch_bounds__(256) transpose_split_kernel(
    const float* __restrict__ W, __nv_bfloat16* __restrict__ Thi,
    __nv_bfloat16* __restrict__ Tlo, int K, int N)
{
    __shared__ float tile[32][33];
    int k0 = blockIdx.y * 32, n0 = blockIdx.x * 32;
    int tx = threadIdx.x & 31, ty = threadIdx.x >> 5;   // 32 x 8
    #pragma unroll
    for (int j = ty; j < 32; j += 8)
        tile[j][tx] = W[(size_t)(k0 + j) * N + n0 + tx];
    __syncthreads();
    #pragma unroll
    for (int j = ty; j < 32; j += 8) {
        float v = tile[tx][j];
        __nv_bfloat16 h = __float2bfloat16(v);
        __nv_bfloat16 l = __float2bfloat16(v - __bfloat162float(h));
        size_t o = (size_t)(n0 + j) * K + k0 + tx;
        Thi[o] = h;
        Tlo[o] = l;
    }
}

// Same, but output padded to Npad rows (rows >= Nsrc are zero).
__global__ void __launch_bounds__(256) transpose_split_pad_kernel(
    const float* __restrict__ W, __nv_bfloat16* __restrict__ Thi,
    __nv_bfloat16* __restrict__ Tlo, int K, int Nsrc)
{
    __shared__ float tile[32][33];
    int k0 = blockIdx.y * 32, n0 = blockIdx.x * 32;
    int tx = threadIdx.x & 31, ty = threadIdx.x >> 5;
    #pragma unroll
    for (int j = ty; j < 32; j += 8)
        tile[j][tx] = (n0 + tx < Nsrc) ? W[(size_t)(k0 + j) * Nsrc + n0 + tx] : 0.f;
    __syncthreads();
    #pragma unroll
    for (int j = ty; j < 32; j += 8) {
        float v = tile[tx][j];
        __nv_bfloat16 h = __float2bfloat16(v);
        __nv_bfloat16 l = __float2bfloat16(v - __bfloat162float(h));
        size_t o = (size_t)(n0 + j) * K + k0 + tx;
        Thi[o] = h;
        Tlo[o] = l;
    }
}

// ---------------- causal depthwise conv1d (K=4) + bias + silu --------------
__global__ void __launch_bounds__(256) conv_silu_kernel(
    const float* __restrict__ conv_w, const float* __restrict__ conv_b)
{
    int idx = blockIdx.x * 256 + threadIdx.x;
    int c  = idx % CONV_DIM;
    int bt = idx / CONV_DIM;
    int t  = bt & (LSEQ - 1);
    float acc = conv_b[c];
    #pragma unroll
    for (int k = 0; k < KCONV; k++) {
        int tt = t - (KCONV - 1) + k;
        if (tt >= 0)
            acc = fmaf(g_xBC[(size_t)(bt - (KCONV - 1) + k) * CONV_DIM + c],
                       conv_w[c * KCONV + k], acc);
    }
    g_xBCc[idx] = acc / (1.f + __expf(-acc));
}

// ---------------- sequential SSM scan: one CTA per (b, head) ---------------
// 256 threads: tid -> p = tid/4, q = tid%4; thread owns state[p, n] for
// n = q*32 + i, i in [0,32)  (vectorized float4 B/C loads).
__global__ void __launch_bounds__(256) scan_kernel(
    const float* __restrict__ dt_bias, const float* __restrict__ A_log,
    const float* __restrict__ Dvec)
{
    int b = blockIdx.x >> 6;
    int h = blockIdx.x & 63;
    int tid = threadIdx.x;
    int p = tid >> 2, q = tid & 3;
    float state[32];
    #pragma unroll
    for (int i = 0; i < 32; i++) state[i] = 0.f;
    const float Ah   = -expf(A_log[h]);
    const float bias = dt_bias[h];
    const float Dh   = Dvec[h];
    __shared__ __align__(16) float sx[2][64];
    __shared__ __align__(16) float sBC[2][256];
    const float* xrow_base = g_xBCc + (size_t)b * LSEQ * CONV_DIM;
    const float* dt_base   = g_dt   + (size_t)b * LSEQ * DTPAD + h;
    float*       y_base    = g_y    + (size_t)b * LSEQ * INTER + h * PDIM;
    float rx = 0.f, rbc, rdt;
    {
        const float* row = xrow_base;
        if (tid < 64) rx = row[h * PDIM + tid];
        rbc = row[INTER + tid];
        rdt = dt_base[0];
    }
    for (int t = 0; t < LSEQ; t++) {
        int buf = t & 1;
        if (tid < 64) sx[buf][tid] = rx;
        sBC[buf][tid] = rbc;
        float dtv = rdt;
        __syncthreads();
        if (t + 1 < LSEQ) {
            const float* row = xrow_base + (size_t)(t + 1) * CONV_DIM;
            if (tid < 64) rx = row[h * PDIM + tid];
            rbc = row[INTER + tid];
            rdt = dt_base[(size_t)(t + 1) * DTPAD];
        }
        float xdt = dtv + bias;
        float sp  = (xdt < 10.f) ? __logf(1.f + __expf(xdt)) : xdt;
        float dA  = __expf(sp * Ah);
        float xv  = sx[buf][p];
        float dtx = sp * xv;
        const float4* B4 = (const float4*)&sBC[buf][0];
        const float4* C4 = (const float4*)&sBC[buf][128];
        float accv = 0.f;
        #pragma unroll
        for (int j = 0; j < 8; j++) {
            float4 bv = B4[q * 8 + j];
            float4 cv = C4[q * 8 + j];
            float s0 = fmaf(state[4*j+0], dA, dtx * bv.x); state[4*j+0] = s0;
            float s1 = fmaf(state[4*j+1], dA, dtx * bv.y); state[4*j+1] = s1;
            float s2 = fmaf(state[4*j+2], dA, dtx * bv.z); state[4*j+2] = s2;
            float s3 = fmaf(state[4*j+3], dA, dtx * bv.w); state[4*j+3] = s3;
            accv = fmaf(s0, cv.x, accv);
            accv = fmaf(s1, cv.y, accv);
            accv = fmaf(s2, cv.z, accv);
            accv = fmaf(s3, cv.w, accv);
        }
        accv += __shfl_xor_sync(0xffffffffu, accv, 1);
        accv += __shfl_xor_sync(0xffffffffu, accv, 2);
        if (q == 0)
            y_base[(size_t)t * INTER + p] = fmaf(Dh, xv, accv);
    }
}

// ---------------- gated RMSNorm + fused bf16 split -------------------------
__global__ void __launch_bounds__(256) norm_kernel(const float* __restrict__ norm_w)
{
    int tok = blockIdx.x;
    __shared__ float sh[INTER];
    __shared__ float sred[8];
    __shared__ float s_scale;
    const float* yrow = g_y    + (size_t)tok * INTER;
    const float* grow = g_gate + (size_t)tok * INTER;
    float ss = 0.f;
    for (int i = threadIdx.x; i < INTER; i += 256) {
        float g  = grow[i];
        float sg = g / (1.f + __expf(-g));
        float hh = yrow[i] * sg;
        sh[i] = hh;
        ss = fmaf(hh, hh, ss);
    }
    #pragma unroll
    for (int o = 16; o; o >>= 1) ss += __shfl_xor_sync(0xffffffffu, ss, o);
    if ((threadIdx.x & 31) == 0) sred[threadIdx.x >> 5] = ss;
    __syncthreads();
    if (threadIdx.x == 0) {
        float tot = 0.f;
        #pragma unroll
        for (int j = 0; j < 8; j++) tot += sred[j];
        s_scale = rsqrtf(tot * (1.f / INTER) + EPS);
    }
    __syncthreads();
    float r = s_scale;
    for (int i = threadIdx.x; i < INTER; i += 256) {
        float val = sh[i] * r * norm_w[i];
        __nv_bfloat16 h = __float2bfloat16(val);
        __nv_bfloat16 l = __float2bfloat16(val - __bfloat162float(h));
        size_t o = (size_t)tok * INTER + i;
        g_norm_hi[o] = h;
        g_norm_lo[o] = l;
    }
}

// ---------------- launch ---------------------------------------------------
extern "C" void kernel_launch(void* const* d_in, const int* in_sizes, int n_in,
                              void* d_out, int out_size)
{
    const float* hs      = (const float*)d_in[0];
    const float* W_z     = (const float*)d_in[1];
    const float* W_xBC   = (const float*)d_in[2];
    const float* W_dt    = (const float*)d_in[3];
    const float* conv_w  = (const float*)d_in[4];
    const float* conv_b  = (const float*)d_in[5];
    const float* dt_bias = (const float*)d_in[6];
    const float* A_log   = (const float*)d_in[7];
    const float* Dv      = (const float*)d_in[8];
    const float* norm_w  = (const float*)d_in[9];
    const float* W_out   = (const float*)d_in[10];
    float* out = (float*)d_out;

    float *p_gate, *p_xBC, *p_dt;
    cudaGetSymbolAddress((void**)&p_gate, g_gate);
    cudaGetSymbolAddress((void**)&p_xBC,  g_xBC);
    cudaGetSymbolAddress((void**)&p_dt,   g_dt);
    __nv_bfloat16 *p_hs_hi, *p_hs_lo, *p_Wz_hi, *p_Wz_lo, *p_Wx_hi, *p_Wx_lo,
                  *p_Wd_hi, *p_Wd_lo, *p_Wo_hi, *p_Wo_lo, *p_nm_hi, *p_nm_lo;
    cudaGetSymbolAddress((void**)&p_hs_hi, g_hs_hi);
    cudaGetSymbolAddress((void**)&p_hs_lo, g_hs_lo);
    cudaGetSymbolAddress((void**)&p_Wz_hi, g_Wz_hi);
    cudaGetSymbolAddress((void**)&p_Wz_lo, g_Wz_lo);
    cudaGetSymbolAddress((void**)&p_Wx_hi, g_WxBC_hi);
    cudaGetSymbolAddress((void**)&p_Wx_lo, g_WxBC_lo);
    cudaGetSymbolAddress((void**)&p_Wd_hi, g_Wdt_hi);
    cudaGetSymbolAddress((void**)&p_Wd_lo, g_Wdt_lo);
    cudaGetSymbolAddress((void**)&p_Wo_hi, g_Wout_hi);
    cudaGetSymbolAddress((void**)&p_Wo_lo, g_Wout_lo);
    cudaGetSymbolAddress((void**)&p_nm_hi, g_norm_hi);
    cudaGetSymbolAddress((void**)&p_nm_lo, g_norm_lo);

    const int GSMEM = 2 * 4 * 16384;   // 131072 B: 2 stages x 4 tiles
    cudaFuncSetAttribute(gemm_mma, cudaFuncAttributeMaxDynamicSharedMemorySize, GSMEM);

    // 0) operand prep
    split8_kernel<<<(TOKENS*DMODEL/8 + 255)/256, 256>>>(hs, p_hs_hi, p_hs_lo, TOKENS*DMODEL);
    transpose_split_kernel<<<dim3(INTER/32, DMODEL/32), 256>>>(W_z, p_Wz_hi, p_Wz_lo, DMODEL, INTER);
    transpose_split_kernel<<<dim3(CONV_DIM/32, DMODEL/32), 256>>>(W_xBC, p_Wx_hi, p_Wx_lo, DMODEL, CONV_DIM);
    transpose_split_pad_kernel<<<dim3(DTPAD/32, DMODEL/32), 256>>>(W_dt, p_Wd_hi, p_Wd_lo, DMODEL, NHEADS);
    transpose_split_kernel<<<dim3(DMODEL/32, INTER/32), 256>>>(W_out, p_Wo_hi, p_Wo_lo, INTER, DMODEL);

    // 1) input projections (HMMA tensor cores)
    gemm_mma<<<dim3(INTER/128, TOKENS/128), 256, GSMEM>>>(
        p_hs_hi, p_hs_lo, p_Wz_hi, p_Wz_lo, p_gate, TOKENS, INTER, DMODEL);
    gemm_mma<<<dim3(CONV_DIM/128, TOKENS/128), 256, GSMEM>>>(
        p_hs_hi, p_hs_lo, p_Wx_hi, p_Wx_lo, p_xBC, TOKENS, CONV_DIM, DMODEL);
    gemm_mma<<<dim3(DTPAD/128, TOKENS/128), 256, GSMEM>>>(
        p_hs_hi, p_hs_lo, p_Wd_hi, p_Wd_lo, p_dt, TOKENS, DTPAD, DMODEL);

    // 2) causal conv + silu
    conv_silu_kernel<<<(TOKENS*CONV_DIM)/256, 256>>>(conv_w, conv_b);
    // 3) SSM scan
    scan_kernel<<<BSZ*NHEADS, 256>>>(dt_bias, A_log, Dv);
    // 4) gated RMSNorm (+ split for out-proj)
    norm_kernel<<<TOKENS, 256>>>(norm_w);
    // 5) output projection (HMMA tensor cores)
    gemm_mma<<<dim3(DMODEL/128, TOKENS/128), 256, GSMEM>>>(
        p_nm_hi, p_nm_lo, p_Wo_hi, p_Wo_lo, out, TOKENS, DMODEL, INTER);
}

// round 5
// speedup vs baseline: 1.4333x; 1.4333x over previous
#include <cuda_runtime.h>
#include <cuda_bf16.h>
#include <math.h>
#include <stdint.h>

// Problem dims
#define BSZ     2
#define LSEQ    2048
#define DMODEL  2048
#define INTER   4096
#define NHEADS  64
#define PDIM    64
#define NSTATE  128
#define KCONV   4
#define CONV_DIM (INTER + 2*NSTATE)   // 4352
#define TOKENS  (BSZ*LSEQ)            // 4096
#define DTPAD   128
#define EPS     1e-5f

// ---------------- scratch (device globals; no allocation allowed) ----------
__device__ __align__(16) float g_gate[TOKENS*INTER];
__device__ __align__(16) float g_xBC[TOKENS*CONV_DIM];
__device__ __align__(16) float g_xBCc[TOKENS*CONV_DIM];
__device__ __align__(16) float g_dt[TOKENS*DTPAD];     // padded to 128 cols
__device__ __align__(16) float g_y[TOKENS*INTER];

// split-bf16 operands for tensor-core GEMMs
__device__ __align__(16) __nv_bfloat16 g_hs_hi[TOKENS*DMODEL];
__device__ __align__(16) __nv_bfloat16 g_hs_lo[TOKENS*DMODEL];
__device__ __align__(16) __nv_bfloat16 g_Wz_hi[INTER*DMODEL];     // transposed [N,K]
__device__ __align__(16) __nv_bfloat16 g_Wz_lo[INTER*DMODEL];
__device__ __align__(16) __nv_bfloat16 g_WxBC_hi[CONV_DIM*DMODEL];
__device__ __align__(16) __nv_bfloat16 g_WxBC_lo[CONV_DIM*DMODEL];
__device__ __align__(16) __nv_bfloat16 g_Wdt_hi[DTPAD*DMODEL];
__device__ __align__(16) __nv_bfloat16 g_Wdt_lo[DTPAD*DMODEL];
__device__ __align__(16) __nv_bfloat16 g_Wout_hi[DMODEL*INTER];
__device__ __align__(16) __nv_bfloat16 g_Wout_lo[DMODEL*INTER];
__device__ __align__(16) __nv_bfloat16 g_norm_hi[TOKENS*INTER];
__device__ __align__(16) __nv_bfloat16 g_norm_lo[TOKENS*INTER];

// ---------------- PTX helpers ----------------------------------------------
__device__ __forceinline__ uint32_t smem_u32(const void* p) {
    uint32_t a;
    asm("{ .reg .u64 t; cvta.to.shared.u64 t, %1; cvt.u32.u64 %0, t; }"
        : "=r"(a) : "l"(p));
    return a;
}
__device__ __forceinline__ void cp16(uint32_t dst, const void* src) {
    asm volatile("cp.async.cg.shared.global [%0], [%1], 16;"
                 :: "r"(dst), "l"(src) : "memory");
}
__device__ __forceinline__ void cp_commit() {
    asm volatile("cp.async.commit_group;" ::: "memory");
}
template<int PENDING>
__device__ __forceinline__ void cp_wait() {
    asm volatile("cp.async.wait_group %0;" :: "n"(PENDING) : "memory");
}
__device__ __forceinline__ void ldm_x4(uint32_t addr, uint32_t* r) {
    asm volatile("ldmatrix.sync.aligned.m8n8.x4.shared.b16 {%0,%1,%2,%3}, [%4];"
                 : "=r"(r[0]), "=r"(r[1]), "=r"(r[2]), "=r"(r[3]) : "r"(addr));
}
__device__ __forceinline__ void mma_bf16(float* c, const uint32_t* a, const uint32_t* b) {
    asm volatile(
        "mma.sync.aligned.m16n8k16.row.col.f32.bf16.bf16.f32 "
        "{%0,%1,%2,%3}, {%4,%5,%6,%7}, {%8,%9}, {%0,%1,%2,%3};"
        : "+f"(c[0]), "+f"(c[1]), "+f"(c[2]), "+f"(c[3])
        : "r"(a[0]), "r"(a[1]), "r"(a[2]), "r"(a[3]), "r"(b[0]), "r"(b[1]));
}

// ---------------- HMMA GEMM: C[M,N] = A[M,K] @ Bt[N,K]^T -------------------
// A, Bt split bf16 (hi, lo); computes HH + HL + LH in fp32 accumulators.
// M, N multiples of 128; K multiple of 64.
__global__ void __launch_bounds__(256) gemm_mma(
    const __nv_bfloat16* __restrict__ Ahi, const __nv_bfloat16* __restrict__ Alo,
    const __nv_bfloat16* __restrict__ Bhi, const __nv_bfloat16* __restrict__ Blo,
    float* __restrict__ C, int M, int N, int K)
{
    extern __shared__ char smem[];
    uint32_t sbase = smem_u32(smem);
    const int TB = 16384;              // one 128x64 bf16 tile (128B rows, SW128)
    const int STAGE = 4 * TB;          // Ahi, Alo, Bhi, Blo

    int tid = threadIdx.x;
    int lane = tid & 31, wid = tid >> 5;
    int wm = wid & 3, wn = wid >> 2;   // warp tile: 32 x 64
    int brow = blockIdx.y * 128, bcol = blockIdx.x * 128;

    const __nv_bfloat16* src0 = Ahi + (size_t)brow * K;
    const __nv_bfloat16* src1 = Alo + (size_t)brow * K;
    const __nv_bfloat16* src2 = Bhi + (size_t)bcol * K;
    const __nv_bfloat16* src3 = Blo + (size_t)bcol * K;
    int nch = K >> 6;

    auto issue = [&](int ch) {
        uint32_t stage = sbase + (uint32_t)(ch & 1) * STAGE;
        const __nv_bfloat16* srcs[4] = {src0, src1, src2, src3};
        #pragma unroll
        for (int t = 0; t < 4; t++) {
            const __nv_bfloat16* P = srcs[t];
            uint32_t tb = stage + (uint32_t)t * TB;
            #pragma unroll
            for (int i = 0; i < 4; i++) {
                int c = tid + i * 256;          // 0..1023 16B chunks
                int row = c >> 3, u = c & 7;
                uint32_t dst = tb + (uint32_t)(row * 128 + ((u ^ (row & 7)) << 4));
                cp16(dst, P + (size_t)row * K + (size_t)ch * 64 + u * 8);
            }
        }
        cp_commit();
    };

    float acc[2][8][4];
    #pragma unroll
    for (int mf = 0; mf < 2; mf++)
        #pragma unroll
        for (int nf = 0; nf < 8; nf++)
            #pragma unroll
            for (int j = 0; j < 4; j++) acc[mf][nf][j] = 0.f;

    issue(0);
    issue(1);

    for (int ch = 0; ch < nch; ch++) {
        if (ch + 1 < nch) cp_wait<1>(); else cp_wait<0>();
        __syncthreads();
        uint32_t stage = sbase + (uint32_t)(ch & 1) * STAGE;

        #pragma unroll
        for (int ks = 0; ks < 4; ks++) {
            uint32_t aH[2][4], aL[2][4];
            #pragma unroll
            for (int mf = 0; mf < 2; mf++) {
                int row = wm * 32 + mf * 16 + (lane & 7) + ((lane >> 3) & 1) * 8;
                int u   = ks * 2 + ((lane >> 4) & 1);
                uint32_t off = (uint32_t)(row * 128 + ((u ^ (row & 7)) << 4));
                ldm_x4(stage + 0 * TB + off, aH[mf]);
                ldm_x4(stage + 1 * TB + off, aL[mf]);
            }
            uint32_t bH[8][2], bL[8][2];
            #pragma unroll
            for (int ng = 0; ng < 4; ng++) {
                int row = wn * 64 + ng * 16 + (lane & 7) + ((lane >> 4) & 1) * 8;
                int u   = ks * 2 + ((lane >> 3) & 1);
                uint32_t off = (uint32_t)(row * 128 + ((u ^ (row & 7)) << 4));
                uint32_t rH[4], rL[4];
                ldm_x4(stage + 2 * TB + off, rH);
                ldm_x4(stage + 3 * TB + off, rL);
                bH[2*ng][0] = rH[0]; bH[2*ng][1] = rH[1];
                bH[2*ng+1][0] = rH[2]; bH[2*ng+1][1] = rH[3];
                bL[2*ng][0] = rL[0]; bL[2*ng][1] = rL[1];
                bL[2*ng+1][0] = rL[2]; bL[2*ng+1][1] = rL[3];
            }
            #pragma unroll
            for (int mf = 0; mf < 2; mf++)
                #pragma unroll
                for (int nf = 0; nf < 8; nf++) {
                    mma_bf16(acc[mf][nf], aH[mf], bH[nf]);
                    mma_bf16(acc[mf][nf], aH[mf], bL[nf]);
                    mma_bf16(acc[mf][nf], aL[mf], bH[nf]);
                }
        }
        __syncthreads();
        if (ch + 2 < nch) issue(ch + 2);
    }

    #pragma unroll
    for (int mf = 0; mf < 2; mf++) {
        int row = brow + wm * 32 + mf * 16 + (lane >> 2);
        #pragma unroll
        for (int nf = 0; nf < 8; nf++) {
            int col = bcol + wn * 64 + nf * 8 + (lane & 3) * 2;
            *(float2*)&C[(size_t)row * N + col] =
                make_float2(acc[mf][nf][0], acc[mf][nf][1]);
            *(float2*)&C[(size_t)(row + 8) * N + col] =
                make_float2(acc[mf][nf][2], acc[mf][nf][3]);
        }
    }
}

// ---------------- fp32 -> (hi,lo) bf16 split, elementwise ------------------
__global__ void __launch_bounds__(256) split8_kernel(
    const float* __restrict__ x, __nv_bfloat16* __restrict__ hi,
    __nv_bfloat16* __restrict__ lo, int n)
{
    int i = (blockIdx.x * 256 + threadIdx.x) * 8;
    if (i >= n) return;
    float4 a = *(const float4*)(x + i);
    float4 b = *(const float4*)(x + i + 4);
    float v[8] = {a.x, a.y, a.z, a.w, b.x, b.y, b.z, b.w};
    uint32_t hp[4], lp[4];
    #pragma unroll
    for (int j = 0; j < 4; j++) {
        __nv_bfloat16 h0 = __float2bfloat16(v[2*j]);
        __nv_bfloat16 h1 = __float2bfloat16(v[2*j+1]);
        __nv_bfloat16 l0 = __float2bfloat16(v[2*j]   - __bfloat162float(h0));
        __nv_bfloat16 l1 = __float2bfloat16(v[2*j+1] - __bfloat162float(h1));
        __nv_bfloat162 hh = __halves2bfloat162(h0, h1);
        __nv_bfloat162 ll = __halves2bfloat162(l0, l1);
        hp[j] = *(uint32_t*)&hh;
        lp[j] = *(uint32_t*)&ll;
    }
    *(uint4*)(hi + i) = make_uint4(hp[0], hp[1], hp[2], hp[3]);
    *(uint4*)(lo + i) = make_uint4(lp[0], lp[1], lp[2], lp[3]);
}

// ---------------- W[K,N] -> Wt[N,K] with bf16 split ------------------------
__global__ void __launch_bounds__(256) transpose_split_kernel(
    const float* __restrict__ W, __nv_bfloat16* __restrict__ Thi,
    __nv_bfloat16* __restrict__ Tlo, int K, int N)
{
    __shared__ float tile[32][33];
    int k0 = blockIdx.y * 32, n0 = blockIdx.x * 32;
    int tx = threadIdx.x & 31, ty = threadIdx.x >> 5;   // 32 x 8
    #pragma unroll
    for (int j = ty; j < 32; j += 8)
        tile[j][tx] = W[(size_t)(k0 + j) * N + n0 + tx];
    __syncthreads();
    #pragma unroll
    for (int j = ty; j < 32; j += 8) {
        float v = tile[tx][j];
        __nv_bfloat16 h = __float2bfloat16(v);
        __nv_bfloat16 l = __float2bfloat16(v - __bfloat162float(h));
        size_t o = (size_t)(n0 + j) * K + k0 + tx;
        Thi[o] = h;
        Tlo[o] = l;
    }
}

// Same, but output padded to Npad rows (rows >= Nsrc are zero).
__global__ void __launch_bounds__(256) transpose_split_pad_kernel(
    const float* __restrict__ W, __nv_bfloat16* __restrict__ Thi,
    __nv_bfloat16* __restrict__ Tlo, int K, int Nsrc)
{
    __shared__ float tile[32][33];
    int k0 = blockIdx.y * 32, n0 = blockIdx.x * 32;
    int tx = threadIdx.x & 31, ty = threadIdx.x >> 5;
    #pragma unroll
    for (int j = ty; j < 32; j += 8)
        tile[j][tx] = (n0 + tx < Nsrc) ? W[(size_t)(k0 + j) * Nsrc + n0 + tx] : 0.f;
    __syncthreads();
    #pragma unroll
    for (int j = ty; j < 32; j += 8) {
        float v = tile[tx][j];
        __nv_bfloat16 h = __float2bfloat16(v);
        __nv_bfloat16 l = __float2bfloat16(v - __bfloat162float(h));
        size_t o = (size_t)(n0 + j) * K + k0 + tx;
        Thi[o] = h;
        Tlo[o] = l;
    }
}

// ---------------- causal depthwise conv1d (K=4) + bias + silu --------------
__global__ void __launch_bounds__(256) conv_silu_kernel(
    const float* __restrict__ conv_w, const float* __restrict__ conv_b)
{
    int idx = blockIdx.x * 256 + threadIdx.x;
    int c  = idx % CONV_DIM;
    int bt = idx / CONV_DIM;
    int t  = bt & (LSEQ - 1);
    float acc = conv_b[c];
    #pragma unroll
    for (int k = 0; k < KCONV; k++) {
        int tt = t - (KCONV - 1) + k;
        if (tt >= 0)
            acc = fmaf(g_xBC[(size_t)(bt - (KCONV - 1) + k) * CONV_DIM + c],
                       conv_w[c * KCONV + k], acc);
    }
    g_xBCc[idx] = acc / (1.f + __expf(-acc));
}

// ---------------- sequential SSM scan: one CTA per (b, head) ---------------
// 256 threads: tid -> p = tid/4, q = tid%4; thread owns state[p, n] for
// n = j*16 + q*4 + e (j in [0,8), e in [0,4)) -> conflict-free LDS.128:
// lane q reads B4[j*4+q], four consecutive 16B chunks across the quad.
__global__ void __launch_bounds__(256) scan_kernel(
    const float* __restrict__ dt_bias, const float* __restrict__ A_log,
    const float* __restrict__ Dvec)
{
    int b = blockIdx.x >> 6;
    int h = blockIdx.x & 63;
    int tid = threadIdx.x;
    int p = tid >> 2, q = tid & 3;
    float state[32];
    #pragma unroll
    for (int i = 0; i < 32; i++) state[i] = 0.f;
    const float Ah   = -expf(A_log[h]);
    const float bias = dt_bias[h];
    const float Dh   = Dvec[h];
    __shared__ __align__(16) float sx[2][64];
    __shared__ __align__(16) float sBC[2][256];
    const float* xrow_base = g_xBCc + (size_t)b * LSEQ * CONV_DIM;
    const float* dt_base   = g_dt   + (size_t)b * LSEQ * DTPAD + h;
    float*       y_base    = g_y    + (size_t)b * LSEQ * INTER + h * PDIM;
    float rx = 0.f, rbc, rdt;
    {
        const float* row = xrow_base;
        if (tid < 64) rx = row[h * PDIM + tid];
        rbc = row[INTER + tid];
        rdt = dt_base[0];
    }
    for (int t = 0; t < LSEQ; t++) {
        int buf = t & 1;
        if (tid < 64) sx[buf][tid] = rx;
        sBC[buf][tid] = rbc;
        float dtv = rdt;
        __syncthreads();
        if (t + 1 < LSEQ) {
            const float* row = xrow_base + (size_t)(t + 1) * CONV_DIM;
            if (tid < 64) rx = row[h * PDIM + tid];
            rbc = row[INTER + tid];
            rdt = dt_base[(size_t)(t + 1) * DTPAD];
        }
        float xdt = dtv + bias;
        float sp  = (xdt < 10.f) ? __logf(1.f + __expf(xdt)) : xdt;
        float dA  = __expf(sp * Ah);
        float xv  = sx[buf][p];
        float dtx = sp * xv;
        const float4* B4 = (const float4*)&sBC[buf][0];
        const float4* C4 = (const float4*)&sBC[buf][128];
        float accv = 0.f;
        #pragma unroll
        for (int j = 0; j < 8; j++) {
            float4 bv = B4[j * 4 + q];
            float4 cv = C4[j * 4 + q];
            float s0 = fmaf(state[4*j+0], dA, dtx * bv.x); state[4*j+0] = s0;
            float s1 = fmaf(state[4*j+1], dA, dtx * bv.y); state[4*j+1] = s1;
            float s2 = fmaf(state[4*j+2], dA, dtx * bv.z); state[4*j+2] = s2;
            float s3 = fmaf(state[4*j+3], dA, dtx * bv.w); state[4*j+3] = s3;
            accv = fmaf(s0, cv.x, accv);
            accv = fmaf(s1, cv.y, accv);
            accv = fmaf(s2, cv.z, accv);
            accv = fmaf(s3, cv.w, accv);
        }
        accv += __shfl_xor_sync(0xffffffffu, accv, 1);
        accv += __shfl_xor_sync(0xffffffffu, accv, 2);
        if (q == 0)
            y_base[(size_t)t * INTER + p] = fmaf(Dh, xv, accv);
    }
}

// ---------------- gated RMSNorm + fused bf16 split -------------------------
__global__ void __launch_bounds__(256) norm_kernel(const float* __restrict__ norm_w)
{
    int tok = blockIdx.x;
    __shared__ float sh[INTER];
    __shared__ float sred[8];
    __shared__ float s_scale;
    const float* yrow = g_y    + (size_t)tok * INTER;
    const float* grow = g_gate + (size_t)tok * INTER;
    float ss = 0.f;
    for (int i = threadIdx.x; i < INTER; i += 256) {
        float g  = grow[i];
        float sg = g / (1.f + __expf(-g));
        float hh = yrow[i] * sg;
        sh[i] = hh;
        ss = fmaf(hh, hh, ss);
    }
    #pragma unroll
    for (int o = 16; o; o >>= 1) ss += __shfl_xor_sync(0xffffffffu, ss, o);
    if ((threadIdx.x & 31) == 0) sred[threadIdx.x >> 5] = ss;
    __syncthreads();
    if (threadIdx.x == 0) {
        float tot = 0.f;
        #pragma unroll
        for (int j = 0; j < 8; j++) tot += sred[j];
        s_scale = rsqrtf(tot * (1.f / INTER) + EPS);
    }
    __syncthreads();
    float r = s_scale;
    for (int i = threadIdx.x; i < INTER; i += 256) {
        float val = sh[i] * r * norm_w[i];
        __nv_bfloat16 h = __float2bfloat16(val);
        __nv_bfloat16 l = __float2bfloat16(val - __bfloat162float(h));
        size_t o = (size_t)tok * INTER + i;
        g_norm_hi[o] = h;
        g_norm_lo[o] = l;
    }
}

// ---------------- launch ---------------------------------------------------
extern "C" void kernel_launch(void* const* d_in, const int* in_sizes, int n_in,
                              void* d_out, int out_size)
{
    const float* hs      = (const float*)d_in[0];
    const float* W_z     = (const float*)d_in[1];
    const float* W_xBC   = (const float*)d_in[2];
    const float* W_dt    = (const float*)d_in[3];
    const float* conv_w  = (const float*)d_in[4];
    const float* conv_b  = (const float*)d_in[5];
    const float* dt_bias = (const float*)d_in[6];
    const float* A_log   = (const float*)d_in[7];
    const float* Dv      = (const float*)d_in[8];
    const float* norm_w  = (const float*)d_in[9];
    const float* W_out   = (const float*)d_in[10];
    float* out = (float*)d_out;

    float *p_gate, *p_xBC, *p_dt;
    cudaGetSymbolAddress((void**)&p_gate, g_gate);
    cudaGetSymbolAddress((void**)&p_xBC,  g_xBC);
    cudaGetSymbolAddress((void**)&p_dt,   g_dt);
    __nv_bfloat16 *p_hs_hi, *p_hs_lo, *p_Wz_hi, *p_Wz_lo, *p_Wx_hi, *p_Wx_lo,
                  *p_Wd_hi, *p_Wd_lo, *p_Wo_hi, *p_Wo_lo, *p_nm_hi, *p_nm_lo;
    cudaGetSymbolAddress((void**)&p_hs_hi, g_hs_hi);
    cudaGetSymbolAddress((void**)&p_hs_lo, g_hs_lo);
    cudaGetSymbolAddress((void**)&p_Wz_hi, g_Wz_hi);
    cudaGetSymbolAddress((void**)&p_Wz_lo, g_Wz_lo);
    cudaGetSymbolAddress((void**)&p_Wx_hi, g_WxBC_hi);
    cudaGetSymbolAddress((void**)&p_Wx_lo, g_WxBC_lo);
    cudaGetSymbolAddress((void**)&p_Wd_hi, g_Wdt_hi);
    cudaGetSymbolAddress((void**)&p_Wd_lo, g_Wdt_lo);
    cudaGetSymbolAddress((void**)&p_Wo_hi, g_Wout_hi);
    cudaGetSymbolAddress((void**)&p_Wo_lo, g_Wout_lo);
    cudaGetSymbolAddress((void**)&p_nm_hi, g_norm_hi);
    cudaGetSymbolAddress((void**)&p_nm_lo, g_norm_lo);

    const int GSMEM = 2 * 4 * 16384;   // 131072 B: 2 stages x 4 tiles
    cudaFuncSetAttribute(gemm_mma, cudaFuncAttributeMaxDynamicSharedMemorySize, GSMEM);

    // 0) operand prep
    split8_kernel<<<(TOKENS*DMODEL/8 + 255)/256, 256>>>(hs, p_hs_hi, p_hs_lo, TOKENS*DMODEL);
    transpose_split_kernel<<<dim3(INTER/32, DMODEL/32), 256>>>(W_z, p_Wz_hi, p_Wz_lo, DMODEL, INTER);
    transpose_split_kernel<<<dim3(CONV_DIM/32, DMODEL/32), 256>>>(W_xBC, p_Wx_hi, p_Wx_lo, DMODEL, CONV_DIM);
    transpose_split_pad_kernel<<<dim3(DTPAD/32, DMODEL/32), 256>>>(W_dt, p_Wd_hi, p_Wd_lo, DMODEL, NHEADS);
    transpose_split_kernel<<<dim3(DMODEL/32, INTER/32), 256>>>(W_out, p_Wo_hi, p_Wo_lo, INTER, DMODEL);

    // 1) input projections (HMMA tensor cores)
    gemm_mma<<<dim3(INTER/128, TOKENS/128), 256, GSMEM>>>(
        p_hs_hi, p_hs_lo, p_Wz_hi, p_Wz_lo, p_gate, TOKENS, INTER, DMODEL);
    gemm_mma<<<dim3(CONV_DIM/128, TOKENS/128), 256, GSMEM>>>(
        p_hs_hi, p_hs_lo, p_Wx_hi, p_Wx_lo, p_xBC, TOKENS, CONV_DIM, DMODEL);
    gemm_mma<<<dim3(DTPAD/128, TOKENS/128), 256, GSMEM>>>(
        p_hs_hi, p_hs_lo, p_Wd_hi, p_Wd_lo, p_dt, TOKENS, DTPAD, DMODEL);

    // 2) causal conv + silu
    conv_silu_kernel<<<(TOKENS*CONV_DIM)/256, 256>>>(conv_w, conv_b);
    // 3) SSM scan
    scan_kernel<<<BSZ*NHEADS, 256>>>(dt_bias, A_log, Dv);
    // 4) gated RMSNorm (+ split for out-proj)
    norm_kernel<<<TOKENS, 256>>>(norm_w);
    // 5) output projection (HMMA tensor cores)
    gemm_mma<<<dim3(DMODEL/128, TOKENS/128), 256, GSMEM>>>(
        p_nm_hi, p_nm_lo, p_Wo_hi, p_Wo_lo, out, TOKENS, DMODEL, INTER);
}

// round 6
// speedup vs baseline: 1.4416x; 1.0058x over previous
#include <cuda_runtime.h>
#include <cuda_bf16.h>
#include <math.h>
#include <stdint.h>

// Problem dims
#define BSZ     2
#define LSEQ    2048
#define DMODEL  2048
#define INTER   4096
#define NHEADS  64
#define PDIM    64
#define NSTATE  128
#define KCONV   4
#define CONV_DIM (INTER + 2*NSTATE)   // 4352
#define TOKENS  (BSZ*LSEQ)            // 4096
#define DTPAD   128
#define EPS     1e-5f

// ---------------- scratch (device globals; no allocation allowed) ----------
__device__ __align__(16) float g_gate[TOKENS*INTER];
__device__ __align__(16) float g_xBC[TOKENS*CONV_DIM];
__device__ __align__(16) float g_xBCc[TOKENS*CONV_DIM];
__device__ __align__(16) float g_dt[TOKENS*DTPAD];     // padded to 128 cols
__device__ __align__(16) float g_y[TOKENS*INTER];

// split-bf16 operands for tensor-core GEMMs
__device__ __align__(16) __nv_bfloat16 g_hs_hi[TOKENS*DMODEL];
__device__ __align__(16) __nv_bfloat16 g_hs_lo[TOKENS*DMODEL];
__device__ __align__(16) __nv_bfloat16 g_Wz_hi[INTER*DMODEL];     // transposed [N,K]
__device__ __align__(16) __nv_bfloat16 g_Wz_lo[INTER*DMODEL];
__device__ __align__(16) __nv_bfloat16 g_WxBC_hi[CONV_DIM*DMODEL];
__device__ __align__(16) __nv_bfloat16 g_WxBC_lo[CONV_DIM*DMODEL];
__device__ __align__(16) __nv_bfloat16 g_Wdt_hi[DTPAD*DMODEL];
__device__ __align__(16) __nv_bfloat16 g_Wdt_lo[DTPAD*DMODEL];
__device__ __align__(16) __nv_bfloat16 g_Wout_hi[DMODEL*INTER];
__device__ __align__(16) __nv_bfloat16 g_Wout_lo[DMODEL*INTER];
__device__ __align__(16) __nv_bfloat16 g_norm_hi[TOKENS*INTER];
__device__ __align__(16) __nv_bfloat16 g_norm_lo[TOKENS*INTER];

// ---------------- PTX helpers ----------------------------------------------
__device__ __forceinline__ uint32_t smem_u32(const void* p) {
    uint32_t a;
    asm("{ .reg .u64 t; cvta.to.shared.u64 t, %1; cvt.u32.u64 %0, t; }"
        : "=r"(a) : "l"(p));
    return a;
}
__device__ __forceinline__ void cp16(uint32_t dst, const void* src) {
    asm volatile("cp.async.cg.shared.global [%0], [%1], 16;"
                 :: "r"(dst), "l"(src) : "memory");
}
__device__ __forceinline__ void cp_commit() {
    asm volatile("cp.async.commit_group;" ::: "memory");
}
template<int PENDING>
__device__ __forceinline__ void cp_wait() {
    asm volatile("cp.async.wait_group %0;" :: "n"(PENDING) : "memory");
}
__device__ __forceinline__ void ldm_x4(uint32_t addr, uint32_t* r) {
    asm volatile("ldmatrix.sync.aligned.m8n8.x4.shared.b16 {%0,%1,%2,%3}, [%4];"
                 : "=r"(r[0]), "=r"(r[1]), "=r"(r[2]), "=r"(r[3]) : "r"(addr));
}
__device__ __forceinline__ void mma_bf16(float* c, const uint32_t* a, const uint32_t* b) {
    asm volatile(
        "mma.sync.aligned.m16n8k16.row.col.f32.bf16.bf16.f32 "
        "{%0,%1,%2,%3}, {%4,%5,%6,%7}, {%8,%9}, {%0,%1,%2,%3};"
        : "+f"(c[0]), "+f"(c[1]), "+f"(c[2]), "+f"(c[3])
        : "r"(a[0]), "r"(a[1]), "r"(a[2]), "r"(a[3]), "r"(b[0]), "r"(b[1]));
}

// ---------------- HMMA GEMM: C[M,N] = A[M,K] @ Bt[N,K]^T -------------------
// A, Bt split bf16 (hi, lo); computes HH + HL + LH in fp32 accumulators.
// BM=256, BN=128, BK=64.  M multiple of 256, N multiple of 128, K mult of 64.
// 8 warps, warp tile 64x64 (wm in [0,4), wn in [0,2)).
#define TB_A 32768            // 256x64 bf16 tile
#define TB_B 16384            // 128x64 bf16 tile
#define STAGE_SZ (2*TB_A + 2*TB_B)   // 98304 B
__global__ void __launch_bounds__(256) gemm_mma(
    const __nv_bfloat16* __restrict__ Ahi, const __nv_bfloat16* __restrict__ Alo,
    const __nv_bfloat16* __restrict__ Bhi, const __nv_bfloat16* __restrict__ Blo,
    float* __restrict__ C, int M, int N, int K)
{
    extern __shared__ char smem[];
    uint32_t sbase = smem_u32(smem);

    int tid = threadIdx.x;
    int lane = tid & 31, wid = tid >> 5;
    int wm = wid & 3, wn = wid >> 2;   // warp tile: 64 x 64
    int brow = blockIdx.y * 256, bcol = blockIdx.x * 128;

    const __nv_bfloat16* srcA0 = Ahi + (size_t)brow * K;
    const __nv_bfloat16* srcA1 = Alo + (size_t)brow * K;
    const __nv_bfloat16* srcB0 = Bhi + (size_t)bcol * K;
    const __nv_bfloat16* srcB1 = Blo + (size_t)bcol * K;
    int nch = K >> 6;

    auto issue = [&](int ch) {
        uint32_t stage = sbase + (uint32_t)(ch & 1) * STAGE_SZ;
        #pragma unroll
        for (int t = 0; t < 2; t++) {      // A hi / A lo: 2048 16B chunks each
            const __nv_bfloat16* P = t ? srcA1 : srcA0;
            uint32_t tb = stage + (uint32_t)t * TB_A;
            #pragma unroll
            for (int i = 0; i < 8; i++) {
                int c = tid + i * 256;
                int row = c >> 3, u = c & 7;
                uint32_t dst = tb + (uint32_t)(row * 128 + ((u ^ (row & 7)) << 4));
                cp16(dst, P + (size_t)row * K + (size_t)ch * 64 + u * 8);
            }
        }
        #pragma unroll
        for (int t = 0; t < 2; t++) {      // B hi / B lo: 1024 16B chunks each
            const __nv_bfloat16* P = t ? srcB1 : srcB0;
            uint32_t tb = stage + 2 * TB_A + (uint32_t)t * TB_B;
            #pragma unroll
            for (int i = 0; i < 4; i++) {
                int c = tid + i * 256;
                int row = c >> 3, u = c & 7;
                uint32_t dst = tb + (uint32_t)(row * 128 + ((u ^ (row & 7)) << 4));
                cp16(dst, P + (size_t)row * K + (size_t)ch * 64 + u * 8);
            }
        }
        cp_commit();
    };

    float acc[4][8][4];
    #pragma unroll
    for (int mf = 0; mf < 4; mf++)
        #pragma unroll
        for (int nf = 0; nf < 8; nf++)
            #pragma unroll
            for (int j = 0; j < 4; j++) acc[mf][nf][j] = 0.f;

    issue(0);
    issue(1);

    for (int ch = 0; ch < nch; ch++) {
        if (ch + 1 < nch) cp_wait<1>(); else cp_wait<0>();
        __syncthreads();
        uint32_t stage = sbase + (uint32_t)(ch & 1) * STAGE_SZ;

        #pragma unroll
        for (int ks = 0; ks < 4; ks++) {
            // B fragments (shared across mf)
            uint32_t bH[8][2], bL[8][2];
            #pragma unroll
            for (int ng = 0; ng < 4; ng++) {
                int row = wn * 64 + ng * 16 + (lane & 7) + ((lane >> 4) & 1) * 8;
                int u   = ks * 2 + ((lane >> 3) & 1);
                uint32_t off = (uint32_t)(row * 128 + ((u ^ (row & 7)) << 4));
                uint32_t rH[4], rL[4];
                ldm_x4(stage + 2 * TB_A + off, rH);
                ldm_x4(stage + 2 * TB_A + TB_B + off, rL);
                bH[2*ng][0] = rH[0]; bH[2*ng][1] = rH[1];
                bH[2*ng+1][0] = rH[2]; bH[2*ng+1][1] = rH[3];
                bL[2*ng][0] = rL[0]; bL[2*ng][1] = rL[1];
                bL[2*ng+1][0] = rL[2]; bL[2*ng+1][1] = rL[3];
            }
            #pragma unroll
            for (int mf = 0; mf < 4; mf++) {
                int row = wm * 64 + mf * 16 + (lane & 7) + ((lane >> 3) & 1) * 8;
                int u   = ks * 2 + ((lane >> 4) & 1);
                uint32_t off = (uint32_t)(row * 128 + ((u ^ (row & 7)) << 4));
                uint32_t aH[4], aL[4];
                ldm_x4(stage + off, aH);
                ldm_x4(stage + TB_A + off, aL);
                #pragma unroll
                for (int nf = 0; nf < 8; nf++) {
                    mma_bf16(acc[mf][nf], aH, bH[nf]);
                    mma_bf16(acc[mf][nf], aH, bL[nf]);
                    mma_bf16(acc[mf][nf], aL, bH[nf]);
                }
            }
        }
        __syncthreads();
        if (ch + 2 < nch) issue(ch + 2);
    }

    #pragma unroll
    for (int mf = 0; mf < 4; mf++) {
        int row = brow + wm * 64 + mf * 16 + (lane >> 2);
        #pragma unroll
        for (int nf = 0; nf < 8; nf++) {
            int col = bcol + wn * 64 + nf * 8 + (lane & 3) * 2;
            *(float2*)&C[(size_t)row * N + col] =
                make_float2(acc[mf][nf][0], acc[mf][nf][1]);
            *(float2*)&C[(size_t)(row + 8) * N + col] =
                make_float2(acc[mf][nf][2], acc[mf][nf][3]);
        }
    }
}

// ---------------- fp32 -> (hi,lo) bf16 split, elementwise ------------------
__global__ void __launch_bounds__(256) split8_kernel(
    const float* __restrict__ x, __nv_bfloat16* __restrict__ hi,
    __nv_bfloat16* __restrict__ lo, int n)
{
    int i = (blockIdx.x * 256 + threadIdx.x) * 8;
    if (i >= n) return;
    float4 a = *(const float4*)(x + i);
    float4 b = *(const float4*)(x + i + 4);
    float v[8] = {a.x, a.y, a.z, a.w, b.x, b.y, b.z, b.w};
    uint32_t hp[4], lp[4];
    #pragma unroll
    for (int j = 0; j < 4; j++) {
        __nv_bfloat16 h0 = __float2bfloat16(v[2*j]);
        __nv_bfloat16 h1 = __float2bfloat16(v[2*j+1]);
        __nv_bfloat16 l0 = __float2bfloat16(v[2*j]   - __bfloat162float(h0));
        __nv_bfloat16 l1 = __float2bfloat16(v[2*j+1] - __bfloat162float(h1));
        __nv_bfloat162 hh = __halves2bfloat162(h0, h1);
        __nv_bfloat162 ll = __halves2bfloat162(l0, l1);
        hp[j] = *(uint32_t*)&hh;
        lp[j] = *(uint32_t*)&ll;
    }
    *(uint4*)(hi + i) = make_uint4(hp[0], hp[1], hp[2], hp[3]);
    *(uint4*)(lo + i) = make_uint4(lp[0], lp[1], lp[2], lp[3]);
}

// ---------------- W[K,N] -> Wt[N,K] with bf16 split ------------------------
__global__ void __launch_bounds__(256) transpose_split_kernel(
    const float* __restrict__ W, __nv_bfloat16* __restrict__ Thi,
    __nv_bfloat16* __restrict__ Tlo, int K, int N)
{
    __shared__ float tile[32][33];
    int k0 = blockIdx.y * 32, n0 = blockIdx.x * 32;
    int tx = threadIdx.x & 31, ty = threadIdx.x >> 5;   // 32 x 8
    #pragma unroll
    for (int j = ty; j < 32; j += 8)
        tile[j][tx] = W[(size_t)(k0 + j) * N + n0 + tx];
    __syncthreads();
    #pragma unroll
    for (int j = ty; j < 32; j += 8) {
        float v = tile[tx][j];
        __nv_bfloat16 h = __float2bfloat16(v);
        __nv_bfloat16 l = __float2bfloat16(v - __bfloat162float(h));
        size_t o = (size_t)(n0 + j) * K + k0 + tx;
        Thi[o] = h;
        Tlo[o] = l;
    }
}

// Same, but reads an [K, Nsrc] matrix into padded [Npad, K] output (zero rows).
__global__ void __launch_bounds__(256) transpose_split_pad_kernel(
    const float* __restrict__ W, __nv_bfloat16* __restrict__ Thi,
    __nv_bfloat16* __restrict__ Tlo, int K, int Nsrc)
{
    __shared__ float tile[32][33];
    int k0 = blockIdx.y * 32, n0 = blockIdx.x * 32;
    int tx = threadIdx.x & 31, ty = threadIdx.x >> 5;
    #pragma unroll
    for (int j = ty; j < 32; j += 8)
        tile[j][tx] = (n0 + tx < Nsrc) ? W[(size_t)(k0 + j) * Nsrc + n0 + tx] : 0.f;
    __syncthreads();
    #pragma unroll
    for (int j = ty; j < 32; j += 8) {
        float v = tile[tx][j];
        __nv_bfloat16 h = __float2bfloat16(v);
        __nv_bfloat16 l = __float2bfloat16(v - __bfloat162float(h));
        size_t o = (size_t)(n0 + j) * K + k0 + tx;
        Thi[o] = h;
        Tlo[o] = l;
    }
}

// ---------------- causal depthwise conv1d (K=4) + bias + silu --------------
__global__ void __launch_bounds__(256) conv_silu_kernel(
    const float* __restrict__ conv_w, const float* __restrict__ conv_b)
{
    int idx = blockIdx.x * 256 + threadIdx.x;
    int c  = idx % CONV_DIM;
    int bt = idx / CONV_DIM;
    int t  = bt & (LSEQ - 1);
    float acc = conv_b[c];
    #pragma unroll
    for (int k = 0; k < KCONV; k++) {
        int tt = t - (KCONV - 1) + k;
        if (tt >= 0)
            acc = fmaf(g_xBC[(size_t)(bt - (KCONV - 1) + k) * CONV_DIM + c],
                       conv_w[c * KCONV + k], acc);
    }
    g_xBCc[idx] = acc / (1.f + __expf(-acc));
}

// ---------------- sequential SSM scan: one CTA per (b, head) ---------------
// n = j*16 + q*4 + e ownership -> conflict-free LDS.128 across the quad.
__global__ void __launch_bounds__(256) scan_kernel(
    const float* __restrict__ dt_bias, const float* __restrict__ A_log,
    const float* __restrict__ Dvec)
{
    int b = blockIdx.x >> 6;
    int h = blockIdx.x & 63;
    int tid = threadIdx.x;
    int p = tid >> 2, q = tid & 3;
    float state[32];
    #pragma unroll
    for (int i = 0; i < 32; i++) state[i] = 0.f;
    const float Ah   = -expf(A_log[h]);
    const float bias = dt_bias[h];
    const float Dh   = Dvec[h];
    __shared__ __align__(16) float sx[2][64];
    __shared__ __align__(16) float sBC[2][256];
    const float* xrow_base = g_xBCc + (size_t)b * LSEQ * CONV_DIM;
    const float* dt_base   = g_dt   + (size_t)b * LSEQ * DTPAD + h;
    float*       y_base    = g_y    + (size_t)b * LSEQ * INTER + h * PDIM;
    float rx = 0.f, rbc, rdt;
    {
        const float* row = xrow_base;
        if (tid < 64) rx = row[h * PDIM + tid];
        rbc = row[INTER + tid];
        rdt = dt_base[0];
    }
    for (int t = 0; t < LSEQ; t++) {
        int buf = t & 1;
        if (tid < 64) sx[buf][tid] = rx;
        sBC[buf][tid] = rbc;
        float dtv = rdt;
        __syncthreads();
        if (t + 1 < LSEQ) {
            const float* row = xrow_base + (size_t)(t + 1) * CONV_DIM;
            if (tid < 64) rx = row[h * PDIM + tid];
            rbc = row[INTER + tid];
            rdt = dt_base[(size_t)(t + 1) * DTPAD];
        }
        float xdt = dtv + bias;
        float sp  = (xdt < 10.f) ? __logf(1.f + __expf(xdt)) : xdt;
        float dA  = __expf(sp * Ah);
        float xv  = sx[buf][p];
        float dtx = sp * xv;
        const float4* B4 = (const float4*)&sBC[buf][0];
        const float4* C4 = (const float4*)&sBC[buf][128];
        float accv = 0.f;
        #pragma unroll
        for (int j = 0; j < 8; j++) {
            float4 bv = B4[j * 4 + q];
            float4 cv = C4[j * 4 + q];
            float s0 = fmaf(state[4*j+0], dA, dtx * bv.x); state[4*j+0] = s0;
            float s1 = fmaf(state[4*j+1], dA, dtx * bv.y); state[4*j+1] = s1;
            float s2 = fmaf(state[4*j+2], dA, dtx * bv.z); state[4*j+2] = s2;
            float s3 = fmaf(state[4*j+3], dA, dtx * bv.w); state[4*j+3] = s3;
            accv = fmaf(s0, cv.x, accv);
            accv = fmaf(s1, cv.y, accv);
            accv = fmaf(s2, cv.z, accv);
            accv = fmaf(s3, cv.w, accv);
        }
        accv += __shfl_xor_sync(0xffffffffu, accv, 1);
        accv += __shfl_xor_sync(0xffffffffu, accv, 2);
        if (q == 0)
            y_base[(size_t)t * INTER + p] = fmaf(Dh, xv, accv);
    }
}

// ---------------- gated RMSNorm + fused bf16 split -------------------------
__global__ void __launch_bounds__(256) norm_kernel(const float* __restrict__ norm_w)
{
    int tok = blockIdx.x;
    __shared__ float sh[INTER];
    __shared__ float sred[8];
    __shared__ float s_scale;
    const float* yrow = g_y    + (size_t)tok * INTER;
    const float* grow = g_gate + (size_t)tok * INTER;
    float ss = 0.f;
    for (int i = threadIdx.x; i < INTER; i += 256) {
        float g  = grow[i];
        float sg = g / (1.f + __expf(-g));
        float hh = yrow[i] * sg;
        sh[i] = hh;
        ss = fmaf(hh, hh, ss);
    }
    #pragma unroll
    for (int o = 16; o; o >>= 1) ss += __shfl_xor_sync(0xffffffffu, ss, o);
    if ((threadIdx.x & 31) == 0) sred[threadIdx.x >> 5] = ss;
    __syncthreads();
    if (threadIdx.x == 0) {
        float tot = 0.f;
        #pragma unroll
        for (int j = 0; j < 8; j++) tot += sred[j];
        s_scale = rsqrtf(tot * (1.f / INTER) + EPS);
    }
    __syncthreads();
    float r = s_scale;
    for (int i = threadIdx.x; i < INTER; i += 256) {
        float val = sh[i] * r * norm_w[i];
        __nv_bfloat16 h = __float2bfloat16(val);
        __nv_bfloat16 l = __float2bfloat16(val - __bfloat162float(h));
        size_t o = (size_t)tok * INTER + i;
        g_norm_hi[o] = h;
        g_norm_lo[o] = l;
    }
}

// ---------------- launch ---------------------------------------------------
extern "C" void kernel_launch(void* const* d_in, const int* in_sizes, int n_in,
                              void* d_out, int out_size)
{
    const float* hs      = (const float*)d_in[0];
    const float* W_z     = (const float*)d_in[1];
    const float* W_xBC   = (const float*)d_in[2];
    const float* W_dt    = (const float*)d_in[3];
    const float* conv_w  = (const float*)d_in[4];
    const float* conv_b  = (const float*)d_in[5];
    const float* dt_bias = (const float*)d_in[6];
    const float* A_log   = (const float*)d_in[7];
    const float* Dv      = (const float*)d_in[8];
    const float* norm_w  = (const float*)d_in[9];
    const float* W_out   = (const float*)d_in[10];
    float* out = (float*)d_out;

    float *p_gate, *p_xBC, *p_dt;
    cudaGetSymbolAddress((void**)&p_gate, g_gate);
    cudaGetSymbolAddress((void**)&p_xBC,  g_xBC);
    cudaGetSymbolAddress((void**)&p_dt,   g_dt);
    __nv_bfloat16 *p_hs_hi, *p_hs_lo, *p_Wz_hi, *p_Wz_lo, *p_Wx_hi, *p_Wx_lo,
                  *p_Wd_hi, *p_Wd_lo, *p_Wo_hi, *p_Wo_lo, *p_nm_hi, *p_nm_lo;
    cudaGetSymbolAddress((void**)&p_hs_hi, g_hs_hi);
    cudaGetSymbolAddress((void**)&p_hs_lo, g_hs_lo);
    cudaGetSymbolAddress((void**)&p_Wz_hi, g_Wz_hi);
    cudaGetSymbolAddress((void**)&p_Wz_lo, g_Wz_lo);
    cudaGetSymbolAddress((void**)&p_Wx_hi, g_WxBC_hi);
    cudaGetSymbolAddress((void**)&p_Wx_lo, g_WxBC_lo);
    cudaGetSymbolAddress((void**)&p_Wd_hi, g_Wdt_hi);
    cudaGetSymbolAddress((void**)&p_Wd_lo, g_Wdt_lo);
    cudaGetSymbolAddress((void**)&p_Wo_hi, g_Wout_hi);
    cudaGetSymbolAddress((void**)&p_Wo_lo, g_Wout_lo);
    cudaGetSymbolAddress((void**)&p_nm_hi, g_norm_hi);
    cudaGetSymbolAddress((void**)&p_nm_lo, g_norm_lo);

    const int GSMEM = 2 * STAGE_SZ;   // 196608 B: 2 stages x (2A + 2B tiles)
    cudaFuncSetAttribute(gemm_mma, cudaFuncAttributeMaxDynamicSharedMemorySize, GSMEM);

    // Launch order chosen so launch index 3 == gemm_mma(W_z) for ncu capture.
    split8_kernel<<<(TOKENS*DMODEL/8 + 255)/256, 256>>>(hs, p_hs_hi, p_hs_lo, TOKENS*DMODEL);        // 0
    transpose_split_kernel<<<dim3(INTER/32, DMODEL/32), 256>>>(W_z, p_Wz_hi, p_Wz_lo, DMODEL, INTER); // 1
    transpose_split_kernel<<<dim3(CONV_DIM/32, DMODEL/32), 256>>>(W_xBC, p_Wx_hi, p_Wx_lo, DMODEL, CONV_DIM); // 2
    gemm_mma<<<dim3(INTER/128, TOKENS/256), 256, GSMEM>>>(                                            // 3
        p_hs_hi, p_hs_lo, p_Wz_hi, p_Wz_lo, p_gate, TOKENS, INTER, DMODEL);
    gemm_mma<<<dim3(CONV_DIM/128, TOKENS/256), 256, GSMEM>>>(                                         // 4
        p_hs_hi, p_hs_lo, p_Wx_hi, p_Wx_lo, p_xBC, TOKENS, CONV_DIM, DMODEL);
    transpose_split_pad_kernel<<<dim3(DTPAD/32, DMODEL/32), 256>>>(W_dt, p_Wd_hi, p_Wd_lo, DMODEL, NHEADS); // 5
    gemm_mma<<<dim3(DTPAD/128, TOKENS/256), 256, GSMEM>>>(                                            // 6
        p_hs_hi, p_hs_lo, p_Wd_hi, p_Wd_lo, p_dt, TOKENS, DTPAD, DMODEL);
    transpose_split_kernel<<<dim3(DMODEL/32, INTER/32), 256>>>(W_out, p_Wo_hi, p_Wo_lo, INTER, DMODEL); // 7
    conv_silu_kernel<<<(TOKENS*CONV_DIM)/256, 256>>>(conv_w, conv_b);                                 // 8
    scan_kernel<<<BSZ*NHEADS, 256>>>(dt_bias, A_log, Dv);                                             // 9
    norm_kernel<<<TOKENS, 256>>>(norm_w);                                                             // 10
    gemm_mma<<<dim3(DMODEL/128, TOKENS/256), 256, GSMEM>>>(                                           // 11
        p_nm_hi, p_nm_lo, p_Wo_hi, p_Wo_lo, out, TOKENS, DMODEL, INTER);
}

// round 7
// speedup vs baseline: 1.4760x; 1.0239x over previous
#include <cuda_runtime.h>
#include <cuda_bf16.h>
#include <math.h>
#include <stdint.h>

// Problem dims
#define BSZ     2
#define LSEQ    2048
#define DMODEL  2048
#define INTER   4096
#define NHEADS  64
#define PDIM    64
#define NSTATE  128
#define KCONV   4
#define CONV_DIM (INTER + 2*NSTATE)   // 4352
#define TOKENS  (BSZ*LSEQ)            // 4096
#define DTPAD   128
#define EPS     1e-5f

// Concatenated input-projection layout: [gate | xBC | dt]
#define NCAT    (INTER + CONV_DIM + DTPAD)   // 8576
#define XBC_OFF INTER                        // 4096
#define DT_OFF  (INTER + CONV_DIM)           // 8448

// ---------------- scratch (device globals; no allocation allowed) ----------
__device__ __align__(16) float g_cat[TOKENS*NCAT];      // fused projections
__device__ __align__(16) float g_xBCc[TOKENS*CONV_DIM]; // post conv+silu
__device__ __align__(16) float g_y[TOKENS*INTER];

// split-bf16 operands for tensor-core GEMMs
__device__ __align__(16) __nv_bfloat16 g_hs_hi[TOKENS*DMODEL];
__device__ __align__(16) __nv_bfloat16 g_hs_lo[TOKENS*DMODEL];
__device__ __align__(16) __nv_bfloat16 g_Wcat_hi[NCAT*DMODEL];   // [Nconcat, K]
__device__ __align__(16) __nv_bfloat16 g_Wcat_lo[NCAT*DMODEL];
__device__ __align__(16) __nv_bfloat16 g_Wout_hi[DMODEL*INTER];
__device__ __align__(16) __nv_bfloat16 g_Wout_lo[DMODEL*INTER];
__device__ __align__(16) __nv_bfloat16 g_norm_hi[TOKENS*INTER];
__device__ __align__(16) __nv_bfloat16 g_norm_lo[TOKENS*INTER];

// ---------------- PTX helpers ----------------------------------------------
__device__ __forceinline__ uint32_t smem_u32(const void* p) {
    uint32_t a;
    asm("{ .reg .u64 t; cvta.to.shared.u64 t, %1; cvt.u32.u64 %0, t; }"
        : "=r"(a) : "l"(p));
    return a;
}
__device__ __forceinline__ void cp16(uint32_t dst, const void* src) {
    asm volatile("cp.async.cg.shared.global [%0], [%1], 16;"
                 :: "r"(dst), "l"(src) : "memory");
}
__device__ __forceinline__ void cp4(uint32_t dst, const void* src) {
    asm volatile("cp.async.ca.shared.global [%0], [%1], 4;"
                 :: "r"(dst), "l"(src) : "memory");
}
__device__ __forceinline__ void cp_commit() {
    asm volatile("cp.async.commit_group;" ::: "memory");
}
template<int PENDING>
__device__ __forceinline__ void cp_wait() {
    asm volatile("cp.async.wait_group %0;" :: "n"(PENDING) : "memory");
}
__device__ __forceinline__ void ldm_x4(uint32_t addr, uint32_t* r) {
    asm volatile("ldmatrix.sync.aligned.m8n8.x4.shared.b16 {%0,%1,%2,%3}, [%4];"
                 : "=r"(r[0]), "=r"(r[1]), "=r"(r[2]), "=r"(r[3]) : "r"(addr));
}
__device__ __forceinline__ void mma_bf16(float* c, const uint32_t* a, const uint32_t* b) {
    asm volatile(
        "mma.sync.aligned.m16n8k16.row.col.f32.bf16.bf16.f32 "
        "{%0,%1,%2,%3}, {%4,%5,%6,%7}, {%8,%9}, {%0,%1,%2,%3};"
        : "+f"(c[0]), "+f"(c[1]), "+f"(c[2]), "+f"(c[3])
        : "r"(a[0]), "r"(a[1]), "r"(a[2]), "r"(a[3]), "r"(b[0]), "r"(b[1]));
}

// ---------------- HMMA GEMM: C[M,N] = A[M,K] @ Bt[N,K]^T -------------------
// BM=256, BN=128, BK=64; 8 warps, warp tile 64x64.
#define TB_A 32768
#define TB_B 16384
#define STAGE_SZ (2*TB_A + 2*TB_B)   // 98304 B
__global__ void __launch_bounds__(256) gemm_mma(
    const __nv_bfloat16* __restrict__ Ahi, const __nv_bfloat16* __restrict__ Alo,
    const __nv_bfloat16* __restrict__ Bhi, const __nv_bfloat16* __restrict__ Blo,
    float* __restrict__ C, int M, int N, int K)
{
    extern __shared__ char smem[];
    uint32_t sbase = smem_u32(smem);

    int tid = threadIdx.x;
    int lane = tid & 31, wid = tid >> 5;
    int wm = wid & 3, wn = wid >> 2;
    int brow = blockIdx.y * 256, bcol = blockIdx.x * 128;

    const __nv_bfloat16* srcA0 = Ahi + (size_t)brow * K;
    const __nv_bfloat16* srcA1 = Alo + (size_t)brow * K;
    const __nv_bfloat16* srcB0 = Bhi + (size_t)bcol * K;
    const __nv_bfloat16* srcB1 = Blo + (size_t)bcol * K;
    int nch = K >> 6;

    auto issue = [&](int ch) {
        uint32_t stage = sbase + (uint32_t)(ch & 1) * STAGE_SZ;
        #pragma unroll
        for (int t = 0; t < 2; t++) {
            const __nv_bfloat16* P = t ? srcA1 : srcA0;
            uint32_t tb = stage + (uint32_t)t * TB_A;
            #pragma unroll
            for (int i = 0; i < 8; i++) {
                int c = tid + i * 256;
                int row = c >> 3, u = c & 7;
                uint32_t dst = tb + (uint32_t)(row * 128 + ((u ^ (row & 7)) << 4));
                cp16(dst, P + (size_t)row * K + (size_t)ch * 64 + u * 8);
            }
        }
        #pragma unroll
        for (int t = 0; t < 2; t++) {
            const __nv_bfloat16* P = t ? srcB1 : srcB0;
            uint32_t tb = stage + 2 * TB_A + (uint32_t)t * TB_B;
            #pragma unroll
            for (int i = 0; i < 4; i++) {
                int c = tid + i * 256;
                int row = c >> 3, u = c & 7;
                uint32_t dst = tb + (uint32_t)(row * 128 + ((u ^ (row & 7)) << 4));
                cp16(dst, P + (size_t)row * K + (size_t)ch * 64 + u * 8);
            }
        }
        cp_commit();
    };

    float acc[4][8][4];
    #pragma unroll
    for (int mf = 0; mf < 4; mf++)
        #pragma unroll
        for (int nf = 0; nf < 8; nf++)
            #pragma unroll
            for (int j = 0; j < 4; j++) acc[mf][nf][j] = 0.f;

    issue(0);
    issue(1);

    for (int ch = 0; ch < nch; ch++) {
        if (ch + 1 < nch) cp_wait<1>(); else cp_wait<0>();
        __syncthreads();
        uint32_t stage = sbase + (uint32_t)(ch & 1) * STAGE_SZ;

        #pragma unroll
        for (int ks = 0; ks < 4; ks++) {
            uint32_t bH[8][2], bL[8][2];
            #pragma unroll
            for (int ng = 0; ng < 4; ng++) {
                int row = wn * 64 + ng * 16 + (lane & 7) + ((lane >> 4) & 1) * 8;
                int u   = ks * 2 + ((lane >> 3) & 1);
                uint32_t off = (uint32_t)(row * 128 + ((u ^ (row & 7)) << 4));
                uint32_t rH[4], rL[4];
                ldm_x4(stage + 2 * TB_A + off, rH);
                ldm_x4(stage + 2 * TB_A + TB_B + off, rL);
                bH[2*ng][0] = rH[0]; bH[2*ng][1] = rH[1];
                bH[2*ng+1][0] = rH[2]; bH[2*ng+1][1] = rH[3];
                bL[2*ng][0] = rL[0]; bL[2*ng][1] = rL[1];
                bL[2*ng+1][0] = rL[2]; bL[2*ng+1][1] = rL[3];
            }
            #pragma unroll
            for (int mf = 0; mf < 4; mf++) {
                int row = wm * 64 + mf * 16 + (lane & 7) + ((lane >> 3) & 1) * 8;
                int u   = ks * 2 + ((lane >> 4) & 1);
                uint32_t off = (uint32_t)(row * 128 + ((u ^ (row & 7)) << 4));
                uint32_t aH[4], aL[4];
                ldm_x4(stage + off, aH);
                ldm_x4(stage + TB_A + off, aL);
                #pragma unroll
                for (int nf = 0; nf < 8; nf++) {
                    mma_bf16(acc[mf][nf], aH, bH[nf]);
                    mma_bf16(acc[mf][nf], aH, bL[nf]);
                    mma_bf16(acc[mf][nf], aL, bH[nf]);
                }
            }
        }
        __syncthreads();
        if (ch + 2 < nch) issue(ch + 2);
    }

    #pragma unroll
    for (int mf = 0; mf < 4; mf++) {
        int row = brow + wm * 64 + mf * 16 + (lane >> 2);
        #pragma unroll
        for (int nf = 0; nf < 8; nf++) {
            int col = bcol + wn * 64 + nf * 8 + (lane & 3) * 2;
            *(float2*)&C[(size_t)row * N + col] =
                make_float2(acc[mf][nf][0], acc[mf][nf][1]);
            *(float2*)&C[(size_t)(row + 8) * N + col] =
                make_float2(acc[mf][nf][2], acc[mf][nf][3]);
        }
    }
}

// ---------------- fp32 -> (hi,lo) bf16 split, elementwise ------------------
__global__ void __launch_bounds__(256) split8_kernel(
    const float* __restrict__ x, __nv_bfloat16* __restrict__ hi,
    __nv_bfloat16* __restrict__ lo, int n)
{
    int i = (blockIdx.x * 256 + threadIdx.x) * 8;
    if (i >= n) return;
    float4 a = *(const float4*)(x + i);
    float4 b = *(const float4*)(x + i + 4);
    float v[8] = {a.x, a.y, a.z, a.w, b.x, b.y, b.z, b.w};
    uint32_t hp[4], lp[4];
    #pragma unroll
    for (int j = 0; j < 4; j++) {
        __nv_bfloat16 h0 = __float2bfloat16(v[2*j]);
        __nv_bfloat16 h1 = __float2bfloat16(v[2*j+1]);
        __nv_bfloat16 l0 = __float2bfloat16(v[2*j]   - __bfloat162float(h0));
        __nv_bfloat16 l1 = __float2bfloat16(v[2*j+1] - __bfloat162float(h1));
        __nv_bfloat162 hh = __halves2bfloat162(h0, h1);
        __nv_bfloat162 ll = __halves2bfloat162(l0, l1);
        hp[j] = *(uint32_t*)&hh;
        lp[j] = *(uint32_t*)&ll;
    }
    *(uint4*)(hi + i) = make_uint4(hp[0], hp[1], hp[2], hp[3]);
    *(uint4*)(lo + i) = make_uint4(lp[0], lp[1], lp[2], lp[3]);
}

// ---------------- W[K,N] -> Wt[N,K] with bf16 split ------------------------
__global__ void __launch_bounds__(256) transpose_split_kernel(
    const float* __restrict__ W, __nv_bfloat16* __restrict__ Thi,
    __nv_bfloat16* __restrict__ Tlo, int K, int N)
{
    __shared__ float tile[32][33];
    int k0 = blockIdx.y * 32, n0 = blockIdx.x * 32;
    int tx = threadIdx.x & 31, ty = threadIdx.x >> 5;
    #pragma unroll
    for (int j = ty; j < 32; j += 8)
        tile[j][tx] = W[(size_t)(k0 + j) * N + n0 + tx];
    __syncthreads();
    #pragma unroll
    for (int j = ty; j < 32; j += 8) {
        float v = tile[tx][j];
        __nv_bfloat16 h = __float2bfloat16(v);
        __nv_bfloat16 l = __float2bfloat16(v - __bfloat162float(h));
        size_t o = (size_t)(n0 + j) * K + k0 + tx;
        Thi[o] = h;
        Tlo[o] = l;
    }
}

// Padded variant: reads [K, Nsrc], writes [Npad, K] (rows >= Nsrc zero).
__global__ void __launch_bounds__(256) transpose_split_pad_kernel(
    const float* __restrict__ W, __nv_bfloat16* __restrict__ Thi,
    __nv_bfloat16* __restrict__ Tlo, int K, int Nsrc)
{
    __shared__ float tile[32][33];
    int k0 = blockIdx.y * 32, n0 = blockIdx.x * 32;
    int tx = threadIdx.x & 31, ty = threadIdx.x >> 5;
    #pragma unroll
    for (int j = ty; j < 32; j += 8)
        tile[j][tx] = (n0 + tx < Nsrc) ? W[(size_t)(k0 + j) * Nsrc + n0 + tx] : 0.f;
    __syncthreads();
    #pragma unroll
    for (int j = ty; j < 32; j += 8) {
        float v = tile[tx][j];
        __nv_bfloat16 h = __float2bfloat16(v);
        __nv_bfloat16 l = __float2bfloat16(v - __bfloat162float(h));
        size_t o = (size_t)(n0 + j) * K + k0 + tx;
        Thi[o] = h;
        Tlo[o] = l;
    }
}

// ---------------- causal depthwise conv1d (K=4) + bias + silu --------------
__global__ void __launch_bounds__(256) conv_silu_kernel(
    const float* __restrict__ conv_w, const float* __restrict__ conv_b)
{
    int idx = blockIdx.x * 256 + threadIdx.x;
    int c  = idx % CONV_DIM;
    int bt = idx / CONV_DIM;
    int t  = bt & (LSEQ - 1);
    float acc = conv_b[c];
    #pragma unroll
    for (int k = 0; k < KCONV; k++) {
        int tt = t - (KCONV - 1) + k;
        if (tt >= 0)
            acc = fmaf(g_cat[(size_t)(bt - (KCONV - 1) + k) * NCAT + XBC_OFF + c],
                       conv_w[c * KCONV + k], acc);
    }
    g_xBCc[idx] = acc / (1.f + __expf(-acc));
}

// ---------------- sequential SSM scan: one CTA per (b, head) ---------------
// Deep cp.async ring (8 stages, prefetch distance 7) hides DRAM latency.
#define SSTG 8
__global__ void __launch_bounds__(256) scan_kernel(
    const float* __restrict__ dt_bias, const float* __restrict__ A_log,
    const float* __restrict__ Dvec)
{
    int b = blockIdx.x >> 6;
    int h = blockIdx.x & 63;
    int tid = threadIdx.x;
    int p = tid >> 2, q = tid & 3;
    float state[32];
    #pragma unroll
    for (int i = 0; i < 32; i++) state[i] = 0.f;
    const float Ah   = -expf(A_log[h]);
    const float bias = dt_bias[h];
    const float Dh   = Dvec[h];

    __shared__ __align__(16) float sx[SSTG][64];
    __shared__ __align__(16) float sBC[SSTG][256];
    __shared__ __align__(16) float sdt[SSTG];

    const float* xbase  = g_xBCc + (size_t)b * LSEQ * CONV_DIM + h * PDIM;
    const float* bcbase = g_xBCc + (size_t)b * LSEQ * CONV_DIM + INTER;
    const float* dtb    = g_cat  + (size_t)b * LSEQ * NCAT + DT_OFF + h;
    float*       y_base = g_y    + (size_t)b * LSEQ * INTER + h * PDIM;

    auto issue = [&](int t) {
        if (t < LSEQ) {
            int slot = t & (SSTG - 1);
            if (tid < 16)
                cp16(smem_u32(&sx[slot][tid * 4]),
                     xbase + (size_t)t * CONV_DIM + tid * 4);
            else if (tid < 80)
                cp16(smem_u32(&sBC[slot][(tid - 16) * 4]),
                     bcbase + (size_t)t * CONV_DIM + (tid - 16) * 4);
            else if (tid == 80)
                cp4(smem_u32(&sdt[slot]), dtb + (size_t)t * NCAT);
        }
        cp_commit();
    };

    #pragma unroll
    for (int t = 0; t < SSTG - 1; t++) issue(t);

    for (int t = 0; t < LSEQ; t++) {
        cp_wait<SSTG - 2>();
        __syncthreads();
        issue(t + SSTG - 1);          // refills slot (t-1)&7: safe post-barrier

        int slot = t & (SSTG - 1);
        float dtv = sdt[slot];
        float xv  = sx[slot][p];
        float xdt = dtv + bias;
        float sp  = (xdt < 10.f) ? __logf(1.f + __expf(xdt)) : xdt;
        float dA  = __expf(sp * Ah);
        float dtx = sp * xv;
        const float4* B4 = (const float4*)&sBC[slot][0];
        const float4* C4 = (const float4*)&sBC[slot][128];
        float accv = 0.f;
        #pragma unroll
        for (int j = 0; j < 8; j++) {
            float4 bv = B4[j * 4 + q];
            float4 cv = C4[j * 4 + q];
            float s0 = fmaf(state[4*j+0], dA, dtx * bv.x); state[4*j+0] = s0;
            float s1 = fmaf(state[4*j+1], dA, dtx * bv.y); state[4*j+1] = s1;
            float s2 = fmaf(state[4*j+2], dA, dtx * bv.z); state[4*j+2] = s2;
            float s3 = fmaf(state[4*j+3], dA, dtx * bv.w); state[4*j+3] = s3;
            accv = fmaf(s0, cv.x, accv);
            accv = fmaf(s1, cv.y, accv);
            accv = fmaf(s2, cv.z, accv);
            accv = fmaf(s3, cv.w, accv);
        }
        accv += __shfl_xor_sync(0xffffffffu, accv, 1);
        accv += __shfl_xor_sync(0xffffffffu, accv, 2);
        if (q == 0)
            y_base[(size_t)t * INTER + p] = fmaf(Dh, xv, accv);
    }
}

// ---------------- gated RMSNorm + fused bf16 split -------------------------
__global__ void __launch_bounds__(256) norm_kernel(const float* __restrict__ norm_w)
{
    int tok = blockIdx.x;
    __shared__ float sh[INTER];
    __shared__ float sred[8];
    __shared__ float s_scale;
    const float* yrow = g_y   + (size_t)tok * INTER;
    const float* grow = g_cat + (size_t)tok * NCAT;      // gate at offset 0
    float ss = 0.f;
    for (int i = threadIdx.x; i < INTER; i += 256) {
        float g  = grow[i];
        float sg = g / (1.f + __expf(-g));
        float hh = yrow[i] * sg;
        sh[i] = hh;
        ss = fmaf(hh, hh, ss);
    }
    #pragma unroll
    for (int o = 16; o; o >>= 1) ss += __shfl_xor_sync(0xffffffffu, ss, o);
    if ((threadIdx.x & 31) == 0) sred[threadIdx.x >> 5] = ss;
    __syncthreads();
    if (threadIdx.x == 0) {
        float tot = 0.f;
        #pragma unroll
        for (int j = 0; j < 8; j++) tot += sred[j];
        s_scale = rsqrtf(tot * (1.f / INTER) + EPS);
    }
    __syncthreads();
    float r = s_scale;
    for (int i = threadIdx.x; i < INTER; i += 256) {
        float val = sh[i] * r * norm_w[i];
        __nv_bfloat16 h = __float2bfloat16(val);
        __nv_bfloat16 l = __float2bfloat16(val - __bfloat162float(h));
        size_t o = (size_t)tok * INTER + i;
        g_norm_hi[o] = h;
        g_norm_lo[o] = l;
    }
}

// ---------------- launch ---------------------------------------------------
extern "C" void kernel_launch(void* const* d_in, const int* in_sizes, int n_in,
                              void* d_out, int out_size)
{
    const float* hs      = (const float*)d_in[0];
    const float* W_z     = (const float*)d_in[1];
    const float* W_xBC   = (const float*)d_in[2];
    const float* W_dt    = (const float*)d_in[3];
    const float* conv_w  = (const float*)d_in[4];
    const float* conv_b  = (const float*)d_in[5];
    const float* dt_bias = (const float*)d_in[6];
    const float* A_log   = (const float*)d_in[7];
    const float* Dv      = (const float*)d_in[8];
    const float* norm_w  = (const float*)d_in[9];
    const float* W_out   = (const float*)d_in[10];
    float* out = (float*)d_out;

    float* p_cat;
    cudaGetSymbolAddress((void**)&p_cat, g_cat);
    __nv_bfloat16 *p_hs_hi, *p_hs_lo, *p_Wc_hi, *p_Wc_lo,
                  *p_Wo_hi, *p_Wo_lo, *p_nm_hi, *p_nm_lo;
    cudaGetSymbolAddress((void**)&p_hs_hi, g_hs_hi);
    cudaGetSymbolAddress((void**)&p_hs_lo, g_hs_lo);
    cudaGetSymbolAddress((void**)&p_Wc_hi, g_Wcat_hi);
    cudaGetSymbolAddress((void**)&p_Wc_lo, g_Wcat_lo);
    cudaGetSymbolAddress((void**)&p_Wo_hi, g_Wout_hi);
    cudaGetSymbolAddress((void**)&p_Wo_lo, g_Wout_lo);
    cudaGetSymbolAddress((void**)&p_nm_hi, g_norm_hi);
    cudaGetSymbolAddress((void**)&p_nm_lo, g_norm_lo);

    const int GSMEM = 2 * STAGE_SZ;   // 196608 B
    cudaFuncSetAttribute(gemm_mma, cudaFuncAttributeMaxDynamicSharedMemorySize, GSMEM);

    // 0) operand prep: all three weights into one concatenated [NCAT, K] buffer
    split8_kernel<<<(TOKENS*DMODEL/8 + 255)/256, 256>>>(hs, p_hs_hi, p_hs_lo, TOKENS*DMODEL); // 0
    transpose_split_kernel<<<dim3(INTER/32, DMODEL/32), 256>>>(                               // 1
        W_z, p_Wc_hi, p_Wc_lo, DMODEL, INTER);
    transpose_split_kernel<<<dim3(CONV_DIM/32, DMODEL/32), 256>>>(                            // 2
        W_xBC, p_Wc_hi + (size_t)XBC_OFF*DMODEL, p_Wc_lo + (size_t)XBC_OFF*DMODEL,
        DMODEL, CONV_DIM);
    transpose_split_pad_kernel<<<dim3(DTPAD/32, DMODEL/32), 256>>>(                           // 3
        W_dt, p_Wc_hi + (size_t)DT_OFF*DMODEL, p_Wc_lo + (size_t)DT_OFF*DMODEL,
        DMODEL, NHEADS);
    // 1) fused input projection GEMM: [gate | xBC | dt] in one launch
    gemm_mma<<<dim3(NCAT/128, TOKENS/256), 256, GSMEM>>>(                                     // 4
        p_hs_hi, p_hs_lo, p_Wc_hi, p_Wc_lo, p_cat, TOKENS, NCAT, DMODEL);
    // 2) causal conv + silu (reads xBC slice of g_cat)
    conv_silu_kernel<<<(TOKENS*CONV_DIM)/256, 256>>>(conv_w, conv_b);                         // 5
    transpose_split_kernel<<<dim3(DMODEL/32, INTER/32), 256>>>(                               // 6
        W_out, p_Wo_hi, p_Wo_lo, INTER, DMODEL);
    // 3) SSM scan (deep-pipelined)
    scan_kernel<<<BSZ*NHEADS, 256>>>(dt_bias, A_log, Dv);                                     // 7
    // 4) gated RMSNorm (+ split for out-proj)
    norm_kernel<<<TOKENS, 256>>>(norm_w);                                                     // 8
    // 5) output projection
    gemm_mma<<<dim3(DMODEL/128, TOKENS/256), 256, GSMEM>>>(                                   // 9
        p_nm_hi, p_nm_lo, p_Wo_hi, p_Wo_lo, out, TOKENS, DMODEL, INTER);
    (void)n_in; (void)in_sizes; (void)out_size;
}

// round 10
// speedup vs baseline: 1.8191x; 1.2325x over previous
#include <cuda_runtime.h>
#include <cuda_bf16.h>
#include <math.h>
#include <stdint.h>

// Problem dims
#define BSZ     2
#define LSEQ    2048
#define DMODEL  2048
#define INTER   4096
#define NHEADS  64
#define PDIM    64
#define NSTATE  128
#define KCONV   4
#define CONV_DIM (INTER + 2*NSTATE)   // 4352
#define TOKENS  (BSZ*LSEQ)            // 4096
#define DTPAD   128
#define EPS     1e-5f

// Concatenated input-projection layout: [gate | xBC | dt]
#define NCAT    (INTER + CONV_DIM + DTPAD)   // 8576
#define XBC_OFF INTER                        // 4096
#define DT_OFF  (INTER + CONV_DIM)           // 8448

// ---------------- scratch (device globals; no allocation allowed) ----------
__device__ __align__(16) float g_cat[TOKENS*NCAT];      // fused projections
__device__ __align__(16) float g_xBCc[TOKENS*CONV_DIM]; // post conv+silu
__device__ __align__(16) float g_y[TOKENS*INTER];
__device__ __align__(16) float2 g_spdA[TOKENS*NHEADS];  // (softplus, dA)

// split-bf16 operands for tensor-core GEMMs
__device__ __align__(16) __nv_bfloat16 g_hs_hi[TOKENS*DMODEL];
__device__ __align__(16) __nv_bfloat16 g_hs_lo[TOKENS*DMODEL];
__device__ __align__(16) __nv_bfloat16 g_Wcat_hi[NCAT*DMODEL];   // [Nconcat, K]
__device__ __align__(16) __nv_bfloat16 g_Wcat_lo[NCAT*DMODEL];
__device__ __align__(16) __nv_bfloat16 g_Wout_hi[DMODEL*INTER];
__device__ __align__(16) __nv_bfloat16 g_Wout_lo[DMODEL*INTER];
__device__ __align__(16) __nv_bfloat16 g_norm_hi[TOKENS*INTER];
__device__ __align__(16) __nv_bfloat16 g_norm_lo[TOKENS*INTER];

// ---------------- PTX helpers ----------------------------------------------
__device__ __forceinline__ uint32_t smem_u32(const void* p) {
    uint32_t a;
    asm("{ .reg .u64 t; cvta.to.shared.u64 t, %1; cvt.u32.u64 %0, t; }"
        : "=r"(a) : "l"(p));
    return a;
}
__device__ __forceinline__ void cp16(uint32_t dst, const void* src) {
    asm volatile("cp.async.cg.shared.global [%0], [%1], 16;"
                 :: "r"(dst), "l"(src) : "memory");
}
__device__ __forceinline__ void cp8(uint32_t dst, const void* src) {
    asm volatile("cp.async.ca.shared.global [%0], [%1], 8;"
                 :: "r"(dst), "l"(src) : "memory");
}
__device__ __forceinline__ void cp_commit() {
    asm volatile("cp.async.commit_group;" ::: "memory");
}
template<int PENDING>
__device__ __forceinline__ void cp_wait() {
    asm volatile("cp.async.wait_group %0;" :: "n"(PENDING) : "memory");
}
__device__ __forceinline__ void ldm_x4(uint32_t addr, uint32_t* r) {
    asm volatile("ldmatrix.sync.aligned.m8n8.x4.shared.b16 {%0,%1,%2,%3}, [%4];"
                 : "=r"(r[0]), "=r"(r[1]), "=r"(r[2]), "=r"(r[3]) : "r"(addr));
}
__device__ __forceinline__ void mma_bf16(float* c, const uint32_t* a, const uint32_t* b) {
    asm volatile(
        "mma.sync.aligned.m16n8k16.row.col.f32.bf16.bf16.f32 "
        "{%0,%1,%2,%3}, {%4,%5,%6,%7}, {%8,%9}, {%0,%1,%2,%3};"
        : "+f"(c[0]), "+f"(c[1]), "+f"(c[2]), "+f"(c[3])
        : "r"(a[0]), "r"(a[1]), "r"(a[2]), "r"(a[3]), "r"(b[0]), "r"(b[1]));
}

// ---------------- HMMA GEMM: C[M,N] = A[M,K] @ Bt[N,K]^T -------------------
// BM=256, BN=128, BK=64; 8 warps, warp tile 64x64.
#define TB_A 32768
#define TB_B 16384
#define STAGE_SZ (2*TB_A + 2*TB_B)   // 98304 B
__global__ void __launch_bounds__(256) gemm_mma(
    const __nv_bfloat16* __restrict__ Ahi, const __nv_bfloat16* __restrict__ Alo,
    const __nv_bfloat16* __restrict__ Bhi, const __nv_bfloat16* __restrict__ Blo,
    float* __restrict__ C, int M, int N, int K)
{
    extern __shared__ char smem[];
    uint32_t sbase = smem_u32(smem);

    int tid = threadIdx.x;
    int lane = tid & 31, wid = tid >> 5;
    int wm = wid & 3, wn = wid >> 2;
    int brow = blockIdx.y * 256, bcol = blockIdx.x * 128;

    const __nv_bfloat16* srcA0 = Ahi + (size_t)brow * K;
    const __nv_bfloat16* srcA1 = Alo + (size_t)brow * K;
    const __nv_bfloat16* srcB0 = Bhi + (size_t)bcol * K;
    const __nv_bfloat16* srcB1 = Blo + (size_t)bcol * K;
    int nch = K >> 6;

    auto issue = [&](int ch) {
        uint32_t stage = sbase + (uint32_t)(ch & 1) * STAGE_SZ;
        #pragma unroll
        for (int t = 0; t < 2; t++) {
            const __nv_bfloat16* P = t ? srcA1 : srcA0;
            uint32_t tb = stage + (uint32_t)t * TB_A;
            #pragma unroll
            for (int i = 0; i < 8; i++) {
                int c = tid + i * 256;
                int row = c >> 3, u = c & 7;
                uint32_t dst = tb + (uint32_t)(row * 128 + ((u ^ (row & 7)) << 4));
                cp16(dst, P + (size_t)row * K + (size_t)ch * 64 + u * 8);
            }
        }
        #pragma unroll
        for (int t = 0; t < 2; t++) {
            const __nv_bfloat16* P = t ? srcB1 : srcB0;
            uint32_t tb = stage + 2 * TB_A + (uint32_t)t * TB_B;
            #pragma unroll
            for (int i = 0; i < 4; i++) {
                int c = tid + i * 256;
                int row = c >> 3, u = c & 7;
                uint32_t dst = tb + (uint32_t)(row * 128 + ((u ^ (row & 7)) << 4));
                cp16(dst, P + (size_t)row * K + (size_t)ch * 64 + u * 8);
            }
        }
        cp_commit();
    };

    float acc[4][8][4];
    #pragma unroll
    for (int mf = 0; mf < 4; mf++)
        #pragma unroll
        for (int nf = 0; nf < 8; nf++)
            #pragma unroll
            for (int j = 0; j < 4; j++) acc[mf][nf][j] = 0.f;

    issue(0);
    issue(1);

    for (int ch = 0; ch < nch; ch++) {
        if (ch + 1 < nch) cp_wait<1>(); else cp_wait<0>();
        __syncthreads();
        uint32_t stage = sbase + (uint32_t)(ch & 1) * STAGE_SZ;

        #pragma unroll
        for (int ks = 0; ks < 4; ks++) {
            uint32_t bH[8][2], bL[8][2];
            #pragma unroll
            for (int ng = 0; ng < 4; ng++) {
                int row = wn * 64 + ng * 16 + (lane & 7) + ((lane >> 4) & 1) * 8;
                int u   = ks * 2 + ((lane >> 3) & 1);
                uint32_t off = (uint32_t)(row * 128 + ((u ^ (row & 7)) << 4));
                uint32_t rH[4], rL[4];
                ldm_x4(stage + 2 * TB_A + off, rH);
                ldm_x4(stage + 2 * TB_A + TB_B + off, rL);
                bH[2*ng][0] = rH[0]; bH[2*ng][1] = rH[1];
                bH[2*ng+1][0] = rH[2]; bH[2*ng+1][1] = rH[3];
                bL[2*ng][0] = rL[0]; bL[2*ng][1] = rL[1];
                bL[2*ng+1][0] = rL[2]; bL[2*ng+1][1] = rL[3];
            }
            #pragma unroll
            for (int mf = 0; mf < 4; mf++) {
                int row = wm * 64 + mf * 16 + (lane & 7) + ((lane >> 3) & 1) * 8;
                int u   = ks * 2 + ((lane >> 4) & 1);
                uint32_t off = (uint32_t)(row * 128 + ((u ^ (row & 7)) << 4));
                uint32_t aH[4], aL[4];
                ldm_x4(stage + off, aH);
                ldm_x4(stage + TB_A + off, aL);
                #pragma unroll
                for (int nf = 0; nf < 8; nf++) {
                    mma_bf16(acc[mf][nf], aH, bH[nf]);
                    mma_bf16(acc[mf][nf], aH, bL[nf]);
                    mma_bf16(acc[mf][nf], aL, bH[nf]);
                }
            }
        }
        __syncthreads();
        if (ch + 2 < nch) issue(ch + 2);
    }

    #pragma unroll
    for (int mf = 0; mf < 4; mf++) {
        int row = brow + wm * 64 + mf * 16 + (lane >> 2);
        #pragma unroll
        for (int nf = 0; nf < 8; nf++) {
            int col = bcol + wn * 64 + nf * 8 + (lane & 3) * 2;
            *(float2*)&C[(size_t)row * N + col] =
                make_float2(acc[mf][nf][0], acc[mf][nf][1]);
            *(float2*)&C[(size_t)(row + 8) * N + col] =
                make_float2(acc[mf][nf][2], acc[mf][nf][3]);
        }
    }
}

// ---------------- fp32 -> (hi,lo) bf16 split, elementwise ------------------
__global__ void __launch_bounds__(256) split8_kernel(
    const float* __restrict__ x, __nv_bfloat16* __restrict__ hi,
    __nv_bfloat16* __restrict__ lo, int n)
{
    int i = (blockIdx.x * 256 + threadIdx.x) * 8;
    if (i >= n) return;
    float4 a = *(const float4*)(x + i);
    float4 b = *(const float4*)(x + i + 4);
    float v[8] = {a.x, a.y, a.z, a.w, b.x, b.y, b.z, b.w};
    uint32_t hp[4], lp[4];
    #pragma unroll
    for (int j = 0; j < 4; j++) {
        __nv_bfloat16 h0 = __float2bfloat16(v[2*j]);
        __nv_bfloat16 h1 = __float2bfloat16(v[2*j+1]);
        __nv_bfloat16 l0 = __float2bfloat16(v[2*j]   - __bfloat162float(h0));
        __nv_bfloat16 l1 = __float2bfloat16(v[2*j+1] - __bfloat162float(h1));
        __nv_bfloat162 hh = __halves2bfloat162(h0, h1);
        __nv_bfloat162 ll = __halves2bfloat162(l0, l1);
        hp[j] = *(uint32_t*)&hh;
        lp[j] = *(uint32_t*)&ll;
    }
    *(uint4*)(hi + i) = make_uint4(hp[0], hp[1], hp[2], hp[3]);
    *(uint4*)(lo + i) = make_uint4(lp[0], lp[1], lp[2], lp[3]);
}

// ---------------- W[K,N] -> Wt[N,K] with bf16 split ------------------------
__global__ void __launch_bounds__(256) transpose_split_kernel(
    const float* __restrict__ W, __nv_bfloat16* __restrict__ Thi,
    __nv_bfloat16* __restrict__ Tlo, int K, int N)
{
    __shared__ float tile[32][33];
    int k0 = blockIdx.y * 32, n0 = blockIdx.x * 32;
    int tx = threadIdx.x & 31, ty = threadIdx.x >> 5;
    #pragma unroll
    for (int j = ty; j < 32; j += 8)
        tile[j][tx] = W[(size_t)(k0 + j) * N + n0 + tx];
    __syncthreads();
    #pragma unroll
    for (int j = ty; j < 32; j += 8) {
        float v = tile[tx][j];
        __nv_bfloat16 h = __float2bfloat16(v);
        __nv_bfloat16 l = __float2bfloat16(v - __bfloat162float(h));
        size_t o = (size_t)(n0 + j) * K + k0 + tx;
        Thi[o] = h;
        Tlo[o] = l;
    }
}

// Padded variant: reads [K, Nsrc], writes [Npad, K] (rows >= Nsrc zero).
__global__ void __launch_bounds__(256) transpose_split_pad_kernel(
    const float* __restrict__ W, __nv_bfloat16* __restrict__ Thi,
    __nv_bfloat16* __restrict__ Tlo, int K, int Nsrc)
{
    __shared__ float tile[32][33];
    int k0 = blockIdx.y * 32, n0 = blockIdx.x * 32;
    int tx = threadIdx.x & 31, ty = threadIdx.x >> 5;
    #pragma unroll
    for (int j = ty; j < 32; j += 8)
        tile[j][tx] = (n0 + tx < Nsrc) ? W[(size_t)(k0 + j) * Nsrc + n0 + tx] : 0.f;
    __syncthreads();
    #pragma unroll
    for (int j = ty; j < 32; j += 8) {
        float v = tile[tx][j];
        __nv_bfloat16 h = __float2bfloat16(v);
        __nv_bfloat16 l = __float2bfloat16(v - __bfloat162float(h));
        size_t o = (size_t)(n0 + j) * K + k0 + tx;
        Thi[o] = h;
        Tlo[o] = l;
    }
}

// ---------------- causal depthwise conv1d (K=4) + bias + silu --------------
__global__ void __launch_bounds__(256) conv_silu_kernel(
    const float* __restrict__ conv_w, const float* __restrict__ conv_b)
{
    int idx = blockIdx.x * 256 + threadIdx.x;
    int c  = idx % CONV_DIM;
    int bt = idx / CONV_DIM;
    int t  = bt & (LSEQ - 1);
    float acc = conv_b[c];
    #pragma unroll
    for (int k = 0; k < KCONV; k++) {
        int tt = t - (KCONV - 1) + k;
        if (tt >= 0)
            acc = fmaf(g_cat[(size_t)(bt - (KCONV - 1) + k) * NCAT + XBC_OFF + c],
                       conv_w[c * KCONV + k], acc);
    }
    g_xBCc[idx] = acc / (1.f + __expf(-acc));
}

// ---------------- softplus/dA precompute: (t,h) -> (sp, dA) ---------------
__global__ void __launch_bounds__(256) spdA_kernel(
    const float* __restrict__ dt_bias, const float* __restrict__ A_log)
{
    int idx = blockIdx.x * 256 + threadIdx.x;     // over TOKENS*NHEADS
    int h  = idx & (NHEADS - 1);
    int bt = idx >> 6;
    float dtv = g_cat[(size_t)bt * NCAT + DT_OFF + h];
    float xdt = dtv + dt_bias[h];
    float sp  = (xdt < 10.f) ? __logf(1.f + __expf(xdt)) : xdt;
    float dA  = __expf(sp * (-__expf(A_log[h])));
    g_spdA[idx] = make_float2(sp, dA);
}

// ---------------- blocked SSM scan: one CTA per (b, head) ------------------
// 8 timesteps per barrier pair; double-buffered 2x8-slot ring; softplus/dA
// precomputed. Ownership n = j*16 + q*4 + e -> conflict-free LDS.128.
__global__ void __launch_bounds__(256) scan_kernel(const float* __restrict__ Dvec)
{
    int b = blockIdx.x >> 6;
    int h = blockIdx.x & 63;
    int tid = threadIdx.x;
    int p = tid >> 2, q = tid & 3;
    float state[32];
    #pragma unroll
    for (int i = 0; i < 32; i++) state[i] = 0.f;
    const float Dh = Dvec[h];

    __shared__ __align__(16) float  sx[16][64];
    __shared__ __align__(16) float  sBC[16][256];
    __shared__ __align__(16) float2 sspdA[16];

    const float*  xbase  = g_xBCc + (size_t)b * LSEQ * CONV_DIM + h * PDIM;
    const float*  bcbase = g_xBCc + (size_t)b * LSEQ * CONV_DIM + INTER;
    const float2* pdA    = g_spdA + (size_t)b * LSEQ * NHEADS + h;
    float*        y_base = g_y    + (size_t)b * LSEQ * INTER + h * PDIM;

    // load 8 steps (group g) into ring half (g&1)
    auto issue_group = [&](int g) {
        int bt0 = g * 8;
        if (bt0 < LSEQ) {
            int half = (g & 1) * 8;
            #pragma unroll
            for (int it = 0; it < 3; it++) {
                int c = tid + it * 256;
                if (c < 640) {
                    int s = c / 80, ch = c % 80;
                    size_t off = (size_t)(bt0 + s) * CONV_DIM;
                    if (ch < 16)
                        cp16(smem_u32(&sx[half + s][ch * 4]), xbase + off + ch * 4);
                    else
                        cp16(smem_u32(&sBC[half + s][(ch - 16) * 4]),
                             bcbase + off + (ch - 16) * 4);
                }
            }
            if (tid < 8)
                cp8(smem_u32(&sspdA[half + tid]), pdA + (size_t)(bt0 + tid) * NHEADS);
        }
        cp_commit();
    };

    issue_group(0);
    issue_group(1);

    for (int g = 0; g < LSEQ / 8; g++) {
        cp_wait<1>();
        __syncthreads();
        int half = (g & 1) * 8;
        #pragma unroll
        for (int s = 0; s < 8; s++) {
            int slot = half + s;
            float2 sd = sspdA[slot];
            float sp = sd.x, dA = sd.y;
            float xv  = sx[slot][p];
            float dtx = sp * xv;
            const float4* B4 = (const float4*)&sBC[slot][0];
            const float4* C4 = (const float4*)&sBC[slot][128];
            float a0 = 0.f, a1 = 0.f, a2 = 0.f, a3 = 0.f;
            #pragma unroll
            for (int j = 0; j < 8; j++) {
                float4 bv = B4[j * 4 + q];
                float4 cv = C4[j * 4 + q];
                float s0 = fmaf(state[4*j+0], dA, dtx * bv.x); state[4*j+0] = s0;
                float s1 = fmaf(state[4*j+1], dA, dtx * bv.y); state[4*j+1] = s1;
                float s2 = fmaf(state[4*j+2], dA, dtx * bv.z); state[4*j+2] = s2;
                float s3 = fmaf(state[4*j+3], dA, dtx * bv.w); state[4*j+3] = s3;
                a0 = fmaf(s0, cv.x, a0);
                a1 = fmaf(s1, cv.y, a1);
                a2 = fmaf(s2, cv.z, a2);
                a3 = fmaf(s3, cv.w, a3);
            }
            float accv = (a0 + a1) + (a2 + a3);
            accv += __shfl_xor_sync(0xffffffffu, accv, 1);
            accv += __shfl_xor_sync(0xffffffffu, accv, 2);
            if (q == 0)
                y_base[(size_t)(g * 8 + s) * INTER + p] = fmaf(Dh, xv, accv);
        }
        __syncthreads();
        issue_group(g + 2);     // refills the half just consumed (post-barrier)
    }
}

// ---------------- gated RMSNorm + fused bf16 split -------------------------
__global__ void __launch_bounds__(256) norm_kernel(const float* __restrict__ norm_w)
{
    int tok = blockIdx.x;
    __shared__ float sh[INTER];
    __shared__ float sred[8];
    __shared__ float s_scale;
    const float* yrow = g_y   + (size_t)tok * INTER;
    const float* grow = g_cat + (size_t)tok * NCAT;      // gate at offset 0
    float ss = 0.f;
    for (int i = threadIdx.x; i < INTER; i += 256) {
        float g  = grow[i];
        float sg = g / (1.f + __expf(-g));
        float hh = yrow[i] * sg;
        sh[i] = hh;
        ss = fmaf(hh, hh, ss);
    }
    #pragma unroll
    for (int o = 16; o; o >>= 1) ss += __shfl_xor_sync(0xffffffffu, ss, o);
    if ((threadIdx.x & 31) == 0) sred[threadIdx.x >> 5] = ss;
    __syncthreads();
    if (threadIdx.x == 0) {
        float tot = 0.f;
        #pragma unroll
        for (int j = 0; j < 8; j++) tot += sred[j];
        s_scale = rsqrtf(tot * (1.f / INTER) + EPS);
    }
    __syncthreads();
    float r = s_scale;
    for (int i = threadIdx.x; i < INTER; i += 256) {
        float val = sh[i] * r * norm_w[i];
        __nv_bfloat16 h = __float2bfloat16(val);
        __nv_bfloat16 l = __float2bfloat16(val - __bfloat162float(h));
        size_t o = (size_t)tok * INTER + i;
        g_norm_hi[o] = h;
        g_norm_lo[o] = l;
    }
}

// ---------------- launch ---------------------------------------------------
extern "C" void kernel_launch(void* const* d_in, const int* in_sizes, int n_in,
                              void* d_out, int out_size)
{
    const float* hs      = (const float*)d_in[0];
    const float* W_z     = (const float*)d_in[1];
    const float* W_xBC   = (const float*)d_in[2];
    const float* W_dt    = (const float*)d_in[3];
    const float* conv_w  = (const float*)d_in[4];
    const float* conv_b  = (const float*)d_in[5];
    const float* dt_bias = (const float*)d_in[6];
    const float* A_log   = (const float*)d_in[7];
    const float* Dv      = (const float*)d_in[8];
    const float* norm_w  = (const float*)d_in[9];
    const float* W_out   = (const float*)d_in[10];
    float* out = (float*)d_out;

    float* p_cat;
    cudaGetSymbolAddress((void**)&p_cat, g_cat);
    __nv_bfloat16 *p_hs_hi, *p_hs_lo, *p_Wc_hi, *p_Wc_lo,
                  *p_Wo_hi, *p_Wo_lo, *p_nm_hi, *p_nm_lo;
    cudaGetSymbolAddress((void**)&p_hs_hi, g_hs_hi);
    cudaGetSymbolAddress((void**)&p_hs_lo, g_hs_lo);
    cudaGetSymbolAddress((void**)&p_Wc_hi, g_Wcat_hi);
    cudaGetSymbolAddress((void**)&p_Wc_lo, g_Wcat_lo);
    cudaGetSymbolAddress((void**)&p_Wo_hi, g_Wout_hi);
    cudaGetSymbolAddress((void**)&p_Wo_lo, g_Wout_lo);
    cudaGetSymbolAddress((void**)&p_nm_hi, g_norm_hi);
    cudaGetSymbolAddress((void**)&p_nm_lo, g_norm_lo);

    const int GSMEM = 2 * STAGE_SZ;   // 196608 B
    cudaFuncSetAttribute(gemm_mma, cudaFuncAttributeMaxDynamicSharedMemorySize, GSMEM);

    // 0) operand prep into one concatenated [NCAT, K] weight buffer
    split8_kernel<<<(TOKENS*DMODEL/8 + 255)/256, 256>>>(hs, p_hs_hi, p_hs_lo, TOKENS*DMODEL);
    transpose_split_kernel<<<dim3(INTER/32, DMODEL/32), 256>>>(
        W_z, p_Wc_hi, p_Wc_lo, DMODEL, INTER);
    transpose_split_kernel<<<dim3(CONV_DIM/32, DMODEL/32), 256>>>(
        W_xBC, p_Wc_hi + (size_t)XBC_OFF*DMODEL, p_Wc_lo + (size_t)XBC_OFF*DMODEL,
        DMODEL, CONV_DIM);
    transpose_split_pad_kernel<<<dim3(DTPAD/32, DMODEL/32), 256>>>(
        W_dt, p_Wc_hi + (size_t)DT_OFF*DMODEL, p_Wc_lo + (size_t)DT_OFF*DMODEL,
        DMODEL, NHEADS);
    // 1) fused input projection GEMM: [gate | xBC | dt]
    gemm_mma<<<dim3(NCAT/128, TOKENS/256), 256, GSMEM>>>(
        p_hs_hi, p_hs_lo, p_Wc_hi, p_Wc_lo, p_cat, TOKENS, NCAT, DMODEL);
    // 2) causal conv + silu, and softplus/dA precompute
    conv_silu_kernel<<<(TOKENS*CONV_DIM)/256, 256>>>(conv_w, conv_b);
    spdA_kernel<<<(TOKENS*NHEADS)/256, 256>>>(dt_bias, A_log);
    transpose_split_kernel<<<dim3(DMODEL/32, INTER/32), 256>>>(
        W_out, p_Wo_hi, p_Wo_lo, INTER, DMODEL);
    // 3) blocked SSM scan
    scan_kernel<<<BSZ*NHEADS, 256>>>(Dv);
    // 4) gated RMSNorm (+ split for out-proj)
    norm_kernel<<<TOKENS, 256>>>(norm_w);
    // 5) output projection
    gemm_mma<<<dim3(DMODEL/128, TOKENS/256), 256, GSMEM>>>(
        p_nm_hi, p_nm_lo, p_Wo_hi, p_Wo_lo, out, TOKENS, DMODEL, INTER);
    (void)n_in; (void)in_sizes; (void)out_size;
}